// round 1
// baseline (speedup 1.0000x reference)
#include <cuda_runtime.h>
#include <math.h>

#define NHEADS 6
#define NTOK   343
#define DIMC   192
#define HD     32
#define NB     256
#define NWIN   64
#define MROWS  (NB*NTOK)      // 87808
#define QKVN   576
#define SCALEF 0.17677669529663687f

// ---- scratch (device globals; no runtime allocation) ----
__device__ float g_q[(size_t)NB*NHEADS*NTOK*HD];
__device__ float g_k[(size_t)NB*NHEADS*NTOK*HD];
__device__ float g_v[(size_t)NB*NHEADS*NTOK*HD];
__device__ float g_bias[(size_t)NHEADS*NTOK*NTOK];
__device__ float g_ao[(size_t)NB*NTOK*DIMC];

// ---------------------------------------------------------------------------
// Kernel 1: expand relative-position-bias table into g_bias[h][i][j]
// ---------------------------------------------------------------------------
__global__ void bias_kernel(const float* __restrict__ rpb)
{
    int i = blockIdx.x;
    int di = i / 49, hi = (i / 7) % 7, wi = i % 7;
    for (int j = threadIdx.x; j < NTOK; j += blockDim.x) {
        int dj = j / 49, hj = (j / 7) % 7, wj = j % 7;
        int idx = (di - dj + 6) * 169 + (hi - hj + 6) * 13 + (wi - wj + 6);
        #pragma unroll
        for (int h = 0; h < NHEADS; h++)
            g_bias[((size_t)h * NTOK + i) * NTOK + j] = rpb[idx * NHEADS + h];
    }
}

// ---------------------------------------------------------------------------
// Kernel 2: QKV GEMM  [MROWS x 192] @ [192 x 576] (+bias), scatter to q/k/v
// BM=128 BN=64 BK=16, 256 threads, 8x4 per thread
// ---------------------------------------------------------------------------
__global__ __launch_bounds__(256) void qkv_gemm(const float* __restrict__ X,
                                                const float* __restrict__ W,
                                                const float* __restrict__ bias)
{
    __shared__ float As[16][129];
    __shared__ float Bs[16][65];
    int tid = threadIdx.x;
    int lr = tid >> 4;        // 0..15
    int lk = tid & 15;        // 0..15
    int ty = tid >> 4;        // row group 0..15 (8 rows each)
    int tx = tid & 15;        // col group 0..15 (4 cols each)
    int m0 = blockIdx.y * 128;
    int n0 = blockIdx.x * 64;

    float c[8][4];
    #pragma unroll
    for (int i = 0; i < 8; i++)
        #pragma unroll
        for (int j = 0; j < 4; j++) c[i][j] = 0.f;

    for (int k0 = 0; k0 < DIMC; k0 += 16) {
        #pragma unroll
        for (int r = 0; r < 8; r++)
            As[lk][lr + r * 16] = X[(size_t)(m0 + lr + r * 16) * DIMC + k0 + lk];
        #pragma unroll
        for (int r = 0; r < 4; r++)
            Bs[lk][lr + r * 16] = W[(size_t)(n0 + lr + r * 16) * DIMC + k0 + lk];
        __syncthreads();
        #pragma unroll
        for (int k = 0; k < 16; k++) {
            float a[8], bb[4];
            #pragma unroll
            for (int i = 0; i < 8; i++) a[i] = As[k][ty * 8 + i];
            #pragma unroll
            for (int j = 0; j < 4; j++) bb[j] = Bs[k][tx * 4 + j];
            #pragma unroll
            for (int i = 0; i < 8; i++)
                #pragma unroll
                for (int j = 0; j < 4; j++) c[i][j] += a[i] * bb[j];
        }
        __syncthreads();
    }

    #pragma unroll
    for (int i = 0; i < 8; i++) {
        int gm = m0 + ty * 8 + i;
        int bI = gm / NTOK, t = gm % NTOK;
        #pragma unroll
        for (int j = 0; j < 4; j++) {
            int gn = n0 + tx * 4 + j;
            float v = c[i][j] + bias[gn];
            int sec = gn / DIMC;
            int rem = gn - sec * DIMC;
            int h = rem >> 5, d = rem & 31;
            size_t off = (((size_t)bI * NHEADS + h) * NTOK + t) * HD + d;
            if (sec == 0)      g_q[off] = v * SCALEF;
            else if (sec == 1) g_k[off] = v;
            else               g_v[off] = v;
        }
    }
}

// ---------------------------------------------------------------------------
// Kernel 3: fused attention. One block per (head, batch-window).
// K,V resident in smem (pad-36 rows), 4 queries per iteration.
// ---------------------------------------------------------------------------
__global__ __launch_bounds__(256) void attn_kernel(const float* __restrict__ mask)
{
    extern __shared__ float sm[];
    float* Ks   = sm;                    // 343*36
    float* Vs   = Ks + NTOK * 36;        // 343*36
    float* ps   = Vs + NTOK * 36;        // 4*344
    float* qs   = ps + 4 * 344;          // 128
    float* red  = qs + 128;              // 1024
    float* wred = red + 1024;            // 32
    float* bmax = wred + 32;             // 4
    float* binv = bmax + 4;              // 4

    int tid  = threadIdx.x;
    int h    = blockIdx.x;
    int b    = blockIdx.y;
    int w    = b & (NWIN - 1);
    int lane = tid & 31, warp = tid >> 5;

    size_t base = (((size_t)b * NHEADS) + h) * NTOK * HD;
    const float* kg = g_k + base;
    const float* vg = g_v + base;
    const float* qg = g_q + base;
    const float* bp = g_bias + (size_t)h * NTOK * NTOK;
    const float* mp = mask + (size_t)w * NTOK * NTOK;

    for (int idx = tid; idx < NTOK * HD; idx += 256) {
        int j = idx >> 5, d = idx & 31;
        Ks[j * 36 + d] = kg[idx];
        Vs[j * 36 + d] = vg[idx];
    }
    // first __syncthreads below (after q load) orders Ks/Vs before use

    int j1 = tid;
    int j2 = tid + 256;
    bool has2 = (j2 < NTOK);
    int j2r = has2 ? j2 : j1;

    for (int tb = 0; tb < 86; tb++) {
        int t0 = tb * 4;
        if (tid < 128) {
            int qi = tid >> 5, d = tid & 31;
            int t = t0 + qi; if (t > NTOK - 1) t = NTOK - 1;
            qs[qi * 32 + d] = qg[t * HD + d];
        }
        __syncthreads();

        // ---- scores for 2 key columns x 4 queries ----
        float s1[4] = {0.f, 0.f, 0.f, 0.f};
        float s2[4] = {0.f, 0.f, 0.f, 0.f};
        #pragma unroll
        for (int d4 = 0; d4 < 8; d4++) {
            float4 k1 = *(const float4*)&Ks[j1 * 36 + d4 * 4];
            float4 k2 = *(const float4*)&Ks[j2r * 36 + d4 * 4];
            #pragma unroll
            for (int qi = 0; qi < 4; qi++) {
                float4 qv = *(const float4*)&qs[qi * 32 + d4 * 4];
                s1[qi] += qv.x * k1.x + qv.y * k1.y + qv.z * k1.z + qv.w * k1.w;
                s2[qi] += qv.x * k2.x + qv.y * k2.y + qv.z * k2.z + qv.w * k2.w;
            }
        }
        #pragma unroll
        for (int qi = 0; qi < 4; qi++) {
            int t = t0 + qi; if (t > NTOK - 1) t = NTOK - 1;
            const float* bprow = bp + (size_t)t * NTOK;
            const float* mprow = mp + (size_t)t * NTOK;
            s1[qi] += bprow[j1] + mprow[j1];
            if (has2) s2[qi] += bprow[j2] + mprow[j2];
        }

        // ---- block max ----
        float m[4];
        #pragma unroll
        for (int qi = 0; qi < 4; qi++)
            m[qi] = has2 ? fmaxf(s1[qi], s2[qi]) : s1[qi];
        #pragma unroll
        for (int o = 16; o; o >>= 1)
            #pragma unroll
            for (int qi = 0; qi < 4; qi++)
                m[qi] = fmaxf(m[qi], __shfl_xor_sync(0xffffffffu, m[qi], o));
        if (lane == 0) {
            #pragma unroll
            for (int qi = 0; qi < 4; qi++) wred[warp * 4 + qi] = m[qi];
        }
        __syncthreads();
        if (tid < 4) {
            float v = wred[tid];
            #pragma unroll
            for (int w2 = 1; w2 < 8; w2++) v = fmaxf(v, wred[w2 * 4 + tid]);
            bmax[tid] = v;
        }
        __syncthreads();

        // ---- exp + sum ----
        float sum[4];
        #pragma unroll
        for (int qi = 0; qi < 4; qi++) {
            float mm = bmax[qi];
            float e1 = __expf(s1[qi] - mm);
            ps[qi * 344 + j1] = e1;
            sum[qi] = e1;
            if (has2) {
                float e2 = __expf(s2[qi] - mm);
                ps[qi * 344 + j2] = e2;
                sum[qi] += e2;
            }
        }
        #pragma unroll
        for (int o = 16; o; o >>= 1)
            #pragma unroll
            for (int qi = 0; qi < 4; qi++)
                sum[qi] += __shfl_xor_sync(0xffffffffu, sum[qi], o);
        if (lane == 0) {
            #pragma unroll
            for (int qi = 0; qi < 4; qi++) wred[warp * 4 + qi] = sum[qi];
        }
        __syncthreads();
        if (tid < 4) {
            float v = 0.f;
            #pragma unroll
            for (int w2 = 0; w2 < 8; w2++) v += wred[w2 * 4 + tid];
            binv[tid] = 1.0f / v;
        }
        __syncthreads();

        // ---- AV ----
        {
            float acc[4] = {0.f, 0.f, 0.f, 0.f};
            for (int j = warp; j < NTOK; j += 8) {
                float vv = Vs[j * 36 + lane];
                #pragma unroll
                for (int qi = 0; qi < 4; qi++)
                    acc[qi] += ps[qi * 344 + j] * vv;
            }
            #pragma unroll
            for (int qi = 0; qi < 4; qi++)
                red[(qi * 8 + warp) * 32 + lane] = acc[qi];
        }
        __syncthreads();
        if (tid < 128) {
            int qi = tid >> 5, d = tid & 31;
            float v = 0.f;
            #pragma unroll
            for (int g2 = 0; g2 < 8; g2++) v += red[(qi * 8 + g2) * 32 + d];
            int t = t0 + qi;
            if (t < NTOK)
                g_ao[((size_t)b * NTOK + t) * DIMC + h * HD + d] = v * binv[qi];
        }
        __syncthreads();
    }
}

// ---------------------------------------------------------------------------
// Kernel 4: projection GEMM  [MROWS x 192] @ [192 x 192] (+bias) -> d_out
// ---------------------------------------------------------------------------
__global__ __launch_bounds__(256) void proj_gemm(const float* __restrict__ W,
                                                 const float* __restrict__ bias,
                                                 float* __restrict__ out)
{
    __shared__ float As[16][129];
    __shared__ float Bs[16][65];
    int tid = threadIdx.x;
    int lr = tid >> 4;
    int lk = tid & 15;
    int ty = tid >> 4;
    int tx = tid & 15;
    int m0 = blockIdx.y * 128;
    int n0 = blockIdx.x * 64;

    float c[8][4];
    #pragma unroll
    for (int i = 0; i < 8; i++)
        #pragma unroll
        for (int j = 0; j < 4; j++) c[i][j] = 0.f;

    for (int k0 = 0; k0 < DIMC; k0 += 16) {
        #pragma unroll
        for (int r = 0; r < 8; r++)
            As[lk][lr + r * 16] = g_ao[(size_t)(m0 + lr + r * 16) * DIMC + k0 + lk];
        #pragma unroll
        for (int r = 0; r < 4; r++)
            Bs[lk][lr + r * 16] = W[(size_t)(n0 + lr + r * 16) * DIMC + k0 + lk];
        __syncthreads();
        #pragma unroll
        for (int k = 0; k < 16; k++) {
            float a[8], bb[4];
            #pragma unroll
            for (int i = 0; i < 8; i++) a[i] = As[k][ty * 8 + i];
            #pragma unroll
            for (int j = 0; j < 4; j++) bb[j] = Bs[k][tx * 4 + j];
            #pragma unroll
            for (int i = 0; i < 8; i++)
                #pragma unroll
                for (int j = 0; j < 4; j++) c[i][j] += a[i] * bb[j];
        }
        __syncthreads();
    }

    #pragma unroll
    for (int i = 0; i < 8; i++) {
        int gm = m0 + ty * 8 + i;
        #pragma unroll
        for (int j = 0; j < 4; j++) {
            int gn = n0 + tx * 4 + j;
            out[(size_t)gm * DIMC + gn] = c[i][j] + bias[gn];
        }
    }
}

// ---------------------------------------------------------------------------
extern "C" void kernel_launch(void* const* d_in, const int* in_sizes, int n_in,
                              void* d_out, int out_size)
{
    const float* x      = (const float*)d_in[0];
    const float* mask   = (const float*)d_in[1];
    const float* qkv_w  = (const float*)d_in[2];
    const float* qkv_b  = (const float*)d_in[3];
    const float* rpb    = (const float*)d_in[4];
    const float* proj_w = (const float*)d_in[5];
    const float* proj_b = (const float*)d_in[6];
    float* out = (float*)d_out;

    (void)in_sizes; (void)n_in; (void)out_size;

    int smem = (NTOK * 36 * 2 + 4 * 344 + 128 + 1024 + 32 + 8) * (int)sizeof(float);
    cudaFuncSetAttribute(attn_kernel, cudaFuncAttributeMaxDynamicSharedMemorySize, smem);

    bias_kernel<<<NTOK, 128>>>(rpb);
    qkv_gemm<<<dim3(QKVN / 64, MROWS / 128), 256>>>(x, qkv_w, qkv_b);
    attn_kernel<<<dim3(NHEADS, NB), 256, smem>>>(mask);
    proj_gemm<<<dim3(DIMC / 64, MROWS / 128), 256>>>(proj_w, proj_b, out);
}

// round 4
// speedup vs baseline: 1.3753x; 1.3753x over previous
#include <cuda_runtime.h>
#include <math.h>

#define NHEADS 6
#define NTOK   343
#define DIMC   192
#define HD     32
#define NB     256
#define NWIN   64
#define MROWS  (NB*NTOK)      // 87808
#define QKVN   576
#define SCALEF 0.17677669529663687f

// smem strides (floats) chosen for conflict-free mma fragment access:
// bank(addr) = addr%32 ; stride%32==4 or 28 -> (4*gid ± qd) all distinct
#define KSTR 36
#define QSTR 36
#define VSTR 356
#define SSTR 348

// ---- scratch (device globals; no runtime allocation) ----
__device__ float g_q[(size_t)NB*NHEADS*NTOK*HD];
__device__ float g_k[(size_t)NB*NHEADS*NTOK*HD];
__device__ float g_v[(size_t)NB*NHEADS*NTOK*HD];
__device__ float g_bias[(size_t)NHEADS*NTOK*NTOK];
__device__ float g_ao[(size_t)NB*NTOK*DIMC];

__device__ __forceinline__ float to_tf32(float x) {
    float r;
    asm("cvt.rna.tf32.f32 %0, %1;" : "=f"(r) : "f"(x));
    return r;
}

__device__ __forceinline__ void mma_tf32(float* c, const float* a, float b0f, float b1f) {
    unsigned A0 = __float_as_uint(a[0]), A1 = __float_as_uint(a[1]);
    unsigned A2 = __float_as_uint(a[2]), A3 = __float_as_uint(a[3]);
    unsigned B0 = __float_as_uint(b0f),  B1 = __float_as_uint(b1f);
    asm volatile(
        "mma.sync.aligned.m16n8k8.row.col.f32.tf32.tf32.f32 "
        "{%0,%1,%2,%3}, {%4,%5,%6,%7}, {%8,%9}, {%0,%1,%2,%3};"
        : "+f"(c[0]), "+f"(c[1]), "+f"(c[2]), "+f"(c[3])
        : "r"(A0), "r"(A1), "r"(A2), "r"(A3), "r"(B0), "r"(B1));
}

// ---------------------------------------------------------------------------
// Kernel 1: expand relative-position-bias table into g_bias[h][i][j]
// ---------------------------------------------------------------------------
__global__ void bias_kernel(const float* __restrict__ rpb)
{
    int i = blockIdx.x;
    int di = i / 49, hi = (i / 7) % 7, wi = i % 7;
    for (int j = threadIdx.x; j < NTOK; j += blockDim.x) {
        int dj = j / 49, hj = (j / 7) % 7, wj = j % 7;
        int idx = (di - dj + 6) * 169 + (hi - hj + 6) * 13 + (wi - wj + 6);
        #pragma unroll
        for (int h = 0; h < NHEADS; h++)
            g_bias[((size_t)h * NTOK + i) * NTOK + j] = rpb[idx * NHEADS + h];
    }
}

// ---------------------------------------------------------------------------
// Kernel 2: QKV GEMM  [MROWS x 192] @ [192 x 576] (+bias), scatter to q/k/v
// Epilogue rounds q/k/v to tf32 (rna) so attention mma inputs are exact tf32.
// ---------------------------------------------------------------------------
__global__ __launch_bounds__(256) void qkv_gemm(const float* __restrict__ X,
                                                const float* __restrict__ W,
                                                const float* __restrict__ bias)
{
    __shared__ float As[16][129];
    __shared__ float Bs[16][65];
    int tid = threadIdx.x;
    int lr = tid >> 4;
    int lk = tid & 15;
    int ty = tid >> 4;
    int tx = tid & 15;
    int m0 = blockIdx.y * 128;
    int n0 = blockIdx.x * 64;

    float c[8][4];
    #pragma unroll
    for (int i = 0; i < 8; i++)
        #pragma unroll
        for (int j = 0; j < 4; j++) c[i][j] = 0.f;

    for (int k0 = 0; k0 < DIMC; k0 += 16) {
        #pragma unroll
        for (int r = 0; r < 8; r++)
            As[lk][lr + r * 16] = X[(size_t)(m0 + lr + r * 16) * DIMC + k0 + lk];
        #pragma unroll
        for (int r = 0; r < 4; r++)
            Bs[lk][lr + r * 16] = W[(size_t)(n0 + lr + r * 16) * DIMC + k0 + lk];
        __syncthreads();
        #pragma unroll
        for (int k = 0; k < 16; k++) {
            float a[8], bb[4];
            #pragma unroll
            for (int i = 0; i < 8; i++) a[i] = As[k][ty * 8 + i];
            #pragma unroll
            for (int j = 0; j < 4; j++) bb[j] = Bs[k][tx * 4 + j];
            #pragma unroll
            for (int i = 0; i < 8; i++)
                #pragma unroll
                for (int j = 0; j < 4; j++) c[i][j] += a[i] * bb[j];
        }
        __syncthreads();
    }

    #pragma unroll
    for (int i = 0; i < 8; i++) {
        int gm = m0 + ty * 8 + i;
        int bI = gm / NTOK, t = gm % NTOK;
        #pragma unroll
        for (int j = 0; j < 4; j++) {
            int gn = n0 + tx * 4 + j;
            float v = c[i][j] + bias[gn];
            int sec = gn / DIMC;
            int rem = gn - sec * DIMC;
            int h = rem >> 5, d = rem & 31;
            size_t off = (((size_t)bI * NHEADS + h) * NTOK + t) * HD + d;
            if (sec == 0)      g_q[off] = to_tf32(v * SCALEF);
            else if (sec == 1) g_k[off] = to_tf32(v);
            else               g_v[off] = to_tf32(v);
        }
    }
}

// ---------------------------------------------------------------------------
// Kernel 3: tensor-core attention (tf32 mma). One block per (head, window).
// K [344][36] and V^T [32][356] resident in smem; 64-query tiles; score strip
// S [64][348] in smem; row softmax; P*V with tf32 mma.
// ---------------------------------------------------------------------------
__global__ __launch_bounds__(256) void attn_tc(const float* __restrict__ mask)
{
    extern __shared__ float sm[];
    float* Ks  = sm;                       // 344*36
    float* Vs  = Ks + 344 * KSTR;          // 32*356  (transposed: [hd][key])
    float* Qs  = Vs + 32 * VSTR;           // 64*36
    float* Ssm = Qs + 64 * QSTR;           // 64*348
    __shared__ float s_binv[64];

    int tid  = threadIdx.x;
    int h    = blockIdx.x;
    int b    = blockIdx.y;
    int w    = b & (NWIN - 1);
    int lane = tid & 31, warp = tid >> 5;
    int gid  = lane >> 2, qd = lane & 3;

    size_t base = (((size_t)b * NHEADS) + h) * NTOK * HD;
    const float* qg = g_q + base;
    const float* kg = g_k + base;
    const float* vg = g_v + base;
    const float* bp = g_bias + (size_t)h * NTOK * NTOK;
    const float* mp = mask + (size_t)w * NTOK * NTOK;

    // fill K (row-major, padded row 343 = 0) and V transposed
    for (int i = tid; i < 344 * 32; i += 256) {
        int j = i >> 5, d = i & 31;
        float kv = 0.f, vv = 0.f;
        if (j < NTOK) { kv = kg[i]; vv = vg[i]; }
        Ks[j * KSTR + d] = kv;
        Vs[d * VSTR + j] = vv;
    }
    __syncthreads();

    int mt = warp & 3;
    int mrow = mt * 16;
    int r0 = mrow + gid, r1 = r0 + 8;

    for (int it = 0; it < 6; it++) {
        int t0 = it * 64;

        // load Q tile (rows past 342 clamped -> duplicates, outputs discarded)
        for (int i = tid; i < 64 * 32; i += 256) {
            int r = i >> 5, d = i & 31;
            int t = t0 + r; if (t > NTOK - 1) t = NTOK - 1;
            Qs[r * QSTR + d] = qg[t * HD + d];
        }
        __syncthreads();

        // ---- QK^T : S[64][344] ----
        float a[4][4];
        #pragma unroll
        for (int ks = 0; ks < 4; ks++) {
            int kc = ks * 8 + qd;
            a[ks][0] = Qs[r0 * QSTR + kc];
            a[ks][1] = Qs[r1 * QSTR + kc];
            a[ks][2] = Qs[r0 * QSTR + kc + 4];
            a[ks][3] = Qs[r1 * QSTR + kc + 4];
        }
        int tA = t0 + r0; if (tA > NTOK - 1) tA = NTOK - 1;
        int tB = t0 + r1; if (tB > NTOK - 1) tB = NTOK - 1;
        const float* bpA = bp + (size_t)tA * NTOK;
        const float* mpA = mp + (size_t)tA * NTOK;
        const float* bpB = bp + (size_t)tB * NTOK;
        const float* mpB = mp + (size_t)tB * NTOK;

        for (int nt = (warp >> 2); nt < 43; nt += 2) {
            int n0 = nt * 8;
            float c[4] = {0.f, 0.f, 0.f, 0.f};
            #pragma unroll
            for (int ks = 0; ks < 4; ks++) {
                int kc = ks * 8 + qd;
                float b0 = Ks[(n0 + gid) * KSTR + kc];
                float b1 = Ks[(n0 + gid) * KSTR + kc + 4];
                mma_tf32(c, a[ks], b0, b1);
            }
            int c0 = n0 + 2 * qd, c1 = c0 + 1;
            float s00 = (c0 < NTOK) ? c[0] + bpA[c0] + mpA[c0] : -1e30f;
            float s01 = (c1 < NTOK) ? c[1] + bpA[c1] + mpA[c1] : -1e30f;
            float s10 = (c0 < NTOK) ? c[2] + bpB[c0] + mpB[c0] : -1e30f;
            float s11 = (c1 < NTOK) ? c[3] + bpB[c1] + mpB[c1] : -1e30f;
            *(float2*)&Ssm[r0 * SSTR + c0] = make_float2(s00, s01);
            *(float2*)&Ssm[r1 * SSTR + c0] = make_float2(s10, s11);
        }
        __syncthreads();

        // ---- row softmax (4 threads per row, quad shuffles) ----
        {
            int r = tid >> 2, sub = tid & 3;
            float* row = Ssm + r * SSTR;
            float mx = -1e30f;
            for (int cidx = sub * 4; cidx < 344; cidx += 16) {
                float4 v4 = *(const float4*)&row[cidx];
                mx = fmaxf(mx, fmaxf(fmaxf(v4.x, v4.y), fmaxf(v4.z, v4.w)));
            }
            mx = fmaxf(mx, __shfl_xor_sync(0xffffffffu, mx, 1));
            mx = fmaxf(mx, __shfl_xor_sync(0xffffffffu, mx, 2));
            float sum = 0.f;
            for (int cidx = sub * 4; cidx < 344; cidx += 16) {
                float4 v4 = *(const float4*)&row[cidx];
                v4.x = __expf(v4.x - mx); v4.y = __expf(v4.y - mx);
                v4.z = __expf(v4.z - mx); v4.w = __expf(v4.w - mx);
                sum += v4.x + v4.y + v4.z + v4.w;
                *(float4*)&row[cidx] = v4;
            }
            sum += __shfl_xor_sync(0xffffffffu, sum, 1);
            sum += __shfl_xor_sync(0xffffffffu, sum, 2);
            if (sub == 0) s_binv[r] = 1.f / sum;
        }
        __syncthreads();

        // ---- A*V : out[64][32] ----
        {
            int npair = (warp >> 2) * 2;
            float cacc[2][4] = {{0.f,0.f,0.f,0.f},{0.f,0.f,0.f,0.f}};
            for (int kt = 0; kt < 43; kt++) {
                int k8 = kt * 8 + qd;
                float pa[4];
                pa[0] = to_tf32(Ssm[r0 * SSTR + k8]);
                pa[1] = to_tf32(Ssm[r1 * SSTR + k8]);
                pa[2] = to_tf32(Ssm[r0 * SSTR + k8 + 4]);
                pa[3] = to_tf32(Ssm[r1 * SSTR + k8 + 4]);
                #pragma unroll
                for (int p = 0; p < 2; p++) {
                    int n0 = (npair + p) * 8;
                    float b0 = Vs[(n0 + gid) * VSTR + k8];
                    float b1 = Vs[(n0 + gid) * VSTR + k8 + 4];
                    mma_tf32(cacc[p], pa, b0, b1);
                }
            }
            int tA2 = t0 + r0, tB2 = t0 + r1;
            float scA = s_binv[r0], scB = s_binv[r1];
            #pragma unroll
            for (int p = 0; p < 2; p++) {
                int col = (npair + p) * 8 + 2 * qd;
                if (tA2 < NTOK)
                    *(float2*)&g_ao[((size_t)b * NTOK + tA2) * DIMC + h * HD + col] =
                        make_float2(cacc[p][0] * scA, cacc[p][1] * scA);
                if (tB2 < NTOK)
                    *(float2*)&g_ao[((size_t)b * NTOK + tB2) * DIMC + h * HD + col] =
                        make_float2(cacc[p][2] * scB, cacc[p][3] * scB);
            }
        }
        __syncthreads();
    }
}

// ---------------------------------------------------------------------------
// Kernel 4: projection GEMM  [MROWS x 192] @ [192 x 192] (+bias) -> d_out
// ---------------------------------------------------------------------------
__global__ __launch_bounds__(256) void proj_gemm(const float* __restrict__ W,
                                                 const float* __restrict__ bias,
                                                 float* __restrict__ out)
{
    __shared__ float As[16][129];
    __shared__ float Bs[16][65];
    int tid = threadIdx.x;
    int lr = tid >> 4;
    int lk = tid & 15;
    int ty = tid >> 4;
    int tx = tid & 15;
    int m0 = blockIdx.y * 128;
    int n0 = blockIdx.x * 64;

    float c[8][4];
    #pragma unroll
    for (int i = 0; i < 8; i++)
        #pragma unroll
        for (int j = 0; j < 4; j++) c[i][j] = 0.f;

    for (int k0 = 0; k0 < DIMC; k0 += 16) {
        #pragma unroll
        for (int r = 0; r < 8; r++)
            As[lk][lr + r * 16] = g_ao[(size_t)(m0 + lr + r * 16) * DIMC + k0 + lk];
        #pragma unroll
        for (int r = 0; r < 4; r++)
            Bs[lk][lr + r * 16] = W[(size_t)(n0 + lr + r * 16) * DIMC + k0 + lk];
        __syncthreads();
        #pragma unroll
        for (int k = 0; k < 16; k++) {
            float a[8], bb[4];
            #pragma unroll
            for (int i = 0; i < 8; i++) a[i] = As[k][ty * 8 + i];
            #pragma unroll
            for (int j = 0; j < 4; j++) bb[j] = Bs[k][tx * 4 + j];
            #pragma unroll
            for (int i = 0; i < 8; i++)
                #pragma unroll
                for (int j = 0; j < 4; j++) c[i][j] += a[i] * bb[j];
        }
        __syncthreads();
    }

    #pragma unroll
    for (int i = 0; i < 8; i++) {
        int gm = m0 + ty * 8 + i;
        #pragma unroll
        for (int j = 0; j < 4; j++) {
            int gn = n0 + tx * 4 + j;
            out[(size_t)gm * DIMC + gn] = c[i][j] + bias[gn];
        }
    }
}

// ---------------------------------------------------------------------------
extern "C" void kernel_launch(void* const* d_in, const int* in_sizes, int n_in,
                              void* d_out, int out_size)
{
    const float* x      = (const float*)d_in[0];
    const float* mask   = (const float*)d_in[1];
    const float* qkv_w  = (const float*)d_in[2];
    const float* qkv_b  = (const float*)d_in[3];
    const float* rpb    = (const float*)d_in[4];
    const float* proj_w = (const float*)d_in[5];
    const float* proj_b = (const float*)d_in[6];
    float* out = (float*)d_out;

    (void)in_sizes; (void)n_in; (void)out_size;

    int smem = (344 * KSTR + 32 * VSTR + 64 * QSTR + 64 * SSTR) * (int)sizeof(float);
    cudaFuncSetAttribute(attn_tc, cudaFuncAttributeMaxDynamicSharedMemorySize, smem);

    bias_kernel<<<NTOK, 128>>>(rpb);
    qkv_gemm<<<dim3(QKVN / 64, MROWS / 128), 256>>>(x, qkv_w, qkv_b);
    attn_tc<<<dim3(NHEADS, NB), 256, smem>>>(mask);
    proj_gemm<<<dim3(DIMC / 64, MROWS / 128), 256>>>(proj_w, proj_b, out);
}

// round 5
// speedup vs baseline: 2.1762x; 1.5823x over previous
#include <cuda_runtime.h>
#include <math.h>

#define NHEADS 6
#define NTOK   343
#define DIMC   192
#define HD     32
#define NB     256
#define NWIN   64
#define MROWS  (NB*NTOK)      // 87808
#define QKVN   576
#define SCALEF 0.17677669529663687f

// smem strides (floats) for conflict-free mma fragment access (stride%32==4)
#define KSTR 36
#define QSTR 36
#define VSTR 356
#define SSTR 348
#define GSTR 36   // gemm smem stride

// ---- scratch (device globals; no runtime allocation) ----
__device__ float g_q[(size_t)NB*NHEADS*NTOK*HD];
__device__ float g_k[(size_t)NB*NHEADS*NTOK*HD];
__device__ float g_v[(size_t)NB*NHEADS*NTOK*HD];
__device__ float g_bm[(size_t)NWIN*NHEADS*NTOK*344];   // bias+mask, row-padded to 344
__device__ float g_ao[(size_t)NB*NTOK*DIMC];

__device__ __forceinline__ float to_tf32(float x) {
    float r;
    asm("cvt.rna.tf32.f32 %0, %1;" : "=f"(r) : "f"(x));
    return r;
}

__device__ __forceinline__ void mma_tf32(float* c, const float* a, float b0f, float b1f) {
    unsigned A0 = __float_as_uint(a[0]), A1 = __float_as_uint(a[1]);
    unsigned A2 = __float_as_uint(a[2]), A3 = __float_as_uint(a[3]);
    unsigned B0 = __float_as_uint(b0f),  B1 = __float_as_uint(b1f);
    asm volatile(
        "mma.sync.aligned.m16n8k8.row.col.f32.tf32.tf32.f32 "
        "{%0,%1,%2,%3}, {%4,%5,%6,%7}, {%8,%9}, {%0,%1,%2,%3};"
        : "+f"(c[0]), "+f"(c[1]), "+f"(c[2]), "+f"(c[3])
        : "r"(A0), "r"(A1), "r"(A2), "r"(A3), "r"(B0), "r"(B1));
}

// ---------------------------------------------------------------------------
// Kernel 1: fuse rpb gather + mask into g_bm[(w*6+h)][i][j] (j padded to 344)
// ---------------------------------------------------------------------------
__global__ void bm_kernel(const float* __restrict__ rpb, const float* __restrict__ mask)
{
    int i  = blockIdx.x;          // 0..342
    int wh = blockIdx.y;          // w*6+h
    int w  = wh / NHEADS, h = wh - w * NHEADS;
    int di = i / 49, hi = (i / 7) % 7, wi = i % 7;
    float* dst = g_bm + ((size_t)wh * NTOK + i) * 344;
    const float* mrow = mask + ((size_t)w * NTOK + i) * NTOK;
    for (int j = threadIdx.x; j < 344; j += 128) {
        if (j < NTOK) {
            int dj = j / 49, hj = (j / 7) % 7, wj = j % 7;
            int idx = (di - dj + 6) * 169 + (hi - hj + 6) * 13 + (wi - wj + 6);
            dst[j] = rpb[idx * NHEADS + h] + mrow[j];
        } else dst[j] = 0.f;
    }
}

// ---------------------------------------------------------------------------
// Kernel 2: tf32-MMA QKV GEMM [MROWS x 192] @ W^T[192 x 576] (+bias), scatter
// BM=128 BN=64 BK=32, 8 warps of 32x32.
// ---------------------------------------------------------------------------
__global__ __launch_bounds__(256) void qkv_gemm_tc(const float* __restrict__ X,
                                                   const float* __restrict__ W,
                                                   const float* __restrict__ bias)
{
    __shared__ float As[128 * GSTR];
    __shared__ float Bs[64 * GSTR];
    int tid = threadIdx.x, lane = tid & 31, warp = tid >> 5;
    int gid = lane >> 2, qd = lane & 3;
    int m0 = blockIdx.y * 128, n0 = blockIdx.x * 64;
    int mrow = (warp & 3) * 32, ncol = (warp >> 2) * 32;
    int arow = tid >> 1, ac0 = (tid & 1) * 16;
    int brow = tid >> 2, bc0 = (tid & 3) * 8;

    float c[2][4][4];
    #pragma unroll
    for (int mt = 0; mt < 2; mt++)
        #pragma unroll
        for (int nt = 0; nt < 4; nt++)
            #pragma unroll
            for (int i = 0; i < 4; i++) c[mt][nt][i] = 0.f;

    for (int k0 = 0; k0 < DIMC; k0 += 32) {
        #pragma unroll
        for (int i = 0; i < 4; i++) {
            float4 v = *(const float4*)&X[(size_t)(m0 + arow) * DIMC + k0 + ac0 + i * 4];
            v.x = to_tf32(v.x); v.y = to_tf32(v.y); v.z = to_tf32(v.z); v.w = to_tf32(v.w);
            *(float4*)&As[arow * GSTR + ac0 + i * 4] = v;
        }
        #pragma unroll
        for (int i = 0; i < 2; i++) {
            float4 v = *(const float4*)&W[(size_t)(n0 + brow) * DIMC + k0 + bc0 + i * 4];
            v.x = to_tf32(v.x); v.y = to_tf32(v.y); v.z = to_tf32(v.z); v.w = to_tf32(v.w);
            *(float4*)&Bs[brow * GSTR + bc0 + i * 4] = v;
        }
        __syncthreads();
        #pragma unroll
        for (int k8 = 0; k8 < 4; k8++) {
            int kk = k8 * 8;
            float a[2][4], b[4][2];
            #pragma unroll
            for (int mt = 0; mt < 2; mt++) {
                int r = mrow + mt * 16 + gid;
                a[mt][0] = As[r * GSTR + kk + qd];
                a[mt][1] = As[(r + 8) * GSTR + kk + qd];
                a[mt][2] = As[r * GSTR + kk + qd + 4];
                a[mt][3] = As[(r + 8) * GSTR + kk + qd + 4];
            }
            #pragma unroll
            for (int nt = 0; nt < 4; nt++) {
                int rn = ncol + nt * 8 + gid;
                b[nt][0] = Bs[rn * GSTR + kk + qd];
                b[nt][1] = Bs[rn * GSTR + kk + qd + 4];
            }
            #pragma unroll
            for (int mt = 0; mt < 2; mt++)
                #pragma unroll
                for (int nt = 0; nt < 4; nt++)
                    mma_tf32(c[mt][nt], a[mt], b[nt][0], b[nt][1]);
        }
        __syncthreads();
    }

    #pragma unroll
    for (int mt = 0; mt < 2; mt++) {
        int gmA = m0 + mrow + mt * 16 + gid, gmB = gmA + 8;
        int bA = gmA / NTOK, tA = gmA - bA * NTOK;
        int bB = gmB / NTOK, tB = gmB - bB * NTOK;
        #pragma unroll
        for (int nt = 0; nt < 4; nt++) {
            int gn = n0 + ncol + nt * 8 + 2 * qd;
            int sec = gn / DIMC, rem = gn - sec * DIMC;
            int hh = rem >> 5, dd = rem & 31;
            float b0 = bias[gn], b1 = bias[gn + 1];
            float vA0 = c[mt][nt][0] + b0, vA1 = c[mt][nt][1] + b1;
            float vB0 = c[mt][nt][2] + b0, vB1 = c[mt][nt][3] + b1;
            size_t offA = (((size_t)bA * NHEADS + hh) * NTOK + tA) * HD + dd;
            size_t offB = (((size_t)bB * NHEADS + hh) * NTOK + tB) * HD + dd;
            if (sec == 0) {
                *(float2*)&g_q[offA] = make_float2(to_tf32(vA0 * SCALEF), to_tf32(vA1 * SCALEF));
                *(float2*)&g_q[offB] = make_float2(to_tf32(vB0 * SCALEF), to_tf32(vB1 * SCALEF));
            } else if (sec == 1) {
                *(float2*)&g_k[offA] = make_float2(to_tf32(vA0), to_tf32(vA1));
                *(float2*)&g_k[offB] = make_float2(to_tf32(vB0), to_tf32(vB1));
            } else {
                *(float2*)&g_v[offA] = make_float2(to_tf32(vA0), to_tf32(vA1));
                *(float2*)&g_v[offB] = make_float2(to_tf32(vB0), to_tf32(vB1));
            }
        }
    }
}

// ---------------------------------------------------------------------------
// Kernel 3: tensor-core attention (tf32 mma). One block per (head, window).
// QK writes RAW scores to Ssm; softmax sweep adds g_bm row (coalesced LDG).
// ---------------------------------------------------------------------------
__global__ __launch_bounds__(256) void attn_tc(const float* __restrict__ mask)
{
    extern __shared__ float sm[];
    float* Ks  = sm;                       // 344*36
    float* Vs  = Ks + 344 * KSTR;          // 32*356  (transposed: [hd][key])
    float* Qs  = Vs + 32 * VSTR;           // 64*36
    float* Ssm = Qs + 64 * QSTR;           // 64*348
    __shared__ float s_binv[64];

    int tid  = threadIdx.x;
    int h    = blockIdx.x;
    int b    = blockIdx.y;
    int w    = b & (NWIN - 1);
    int lane = tid & 31, warp = tid >> 5;
    int gid  = lane >> 2, qd = lane & 3;

    size_t base = (((size_t)b * NHEADS) + h) * NTOK * HD;
    const float* qg = g_q + base;
    const float* kg = g_k + base;
    const float* vg = g_v + base;
    const float* bm = g_bm + (size_t)(w * NHEADS + h) * NTOK * 344;

    for (int i = tid; i < 344 * 32; i += 256) {
        int j = i >> 5, d = i & 31;
        float kv = 0.f, vv = 0.f;
        if (j < NTOK) { kv = kg[i]; vv = vg[i]; }
        Ks[j * KSTR + d] = kv;
        Vs[d * VSTR + j] = vv;
    }
    __syncthreads();

    int mt = warp & 3;
    int mrow = mt * 16;
    int r0 = mrow + gid, r1 = r0 + 8;

    for (int it = 0; it < 6; it++) {
        int t0 = it * 64;

        for (int i = tid; i < 64 * 32; i += 256) {
            int r = i >> 5, d = i & 31;
            int t = t0 + r; if (t > NTOK - 1) t = NTOK - 1;
            Qs[r * QSTR + d] = qg[t * HD + d];
        }
        __syncthreads();

        // ---- QK^T : raw scores ----
        float a[4][4];
        #pragma unroll
        for (int ks = 0; ks < 4; ks++) {
            int kc = ks * 8 + qd;
            a[ks][0] = Qs[r0 * QSTR + kc];
            a[ks][1] = Qs[r1 * QSTR + kc];
            a[ks][2] = Qs[r0 * QSTR + kc + 4];
            a[ks][3] = Qs[r1 * QSTR + kc + 4];
        }
        for (int nt = (warp >> 2); nt < 43; nt += 2) {
            int n0 = nt * 8;
            float c[4] = {0.f, 0.f, 0.f, 0.f};
            #pragma unroll
            for (int ks = 0; ks < 4; ks++) {
                int kc = ks * 8 + qd;
                float b0 = Ks[(n0 + gid) * KSTR + kc];
                float b1 = Ks[(n0 + gid) * KSTR + kc + 4];
                mma_tf32(c, a[ks], b0, b1);
            }
            int c0 = n0 + 2 * qd, c1 = c0 + 1;
            float s00 = (c0 < NTOK) ? c[0] : -1e30f;
            float s01 = (c1 < NTOK) ? c[1] : -1e30f;
            float s10 = (c0 < NTOK) ? c[2] : -1e30f;
            float s11 = (c1 < NTOK) ? c[3] : -1e30f;
            *(float2*)&Ssm[r0 * SSTR + c0] = make_float2(s00, s01);
            *(float2*)&Ssm[r1 * SSTR + c0] = make_float2(s10, s11);
        }
        __syncthreads();

        // ---- row softmax: add bm row (coalesced global) + max/exp/sum ----
        {
            int r = tid >> 2, sub = tid & 3;
            int t = t0 + r; if (t > NTOK - 1) t = NTOK - 1;
            float* row = Ssm + r * SSTR;
            const float* bmr = bm + (size_t)t * 344;
            float mx = -1e30f;
            for (int cidx = sub * 4; cidx < 344; cidx += 16) {
                float4 v4 = *(const float4*)&row[cidx];
                float4 b4 = *(const float4*)&bmr[cidx];
                v4.x += b4.x; v4.y += b4.y; v4.z += b4.z; v4.w += b4.w;
                *(float4*)&row[cidx] = v4;
                mx = fmaxf(mx, fmaxf(fmaxf(v4.x, v4.y), fmaxf(v4.z, v4.w)));
            }
            mx = fmaxf(mx, __shfl_xor_sync(0xffffffffu, mx, 1));
            mx = fmaxf(mx, __shfl_xor_sync(0xffffffffu, mx, 2));
            float sum = 0.f;
            for (int cidx = sub * 4; cidx < 344; cidx += 16) {
                float4 v4 = *(const float4*)&row[cidx];
                v4.x = __expf(v4.x - mx); v4.y = __expf(v4.y - mx);
                v4.z = __expf(v4.z - mx); v4.w = __expf(v4.w - mx);
                sum += v4.x + v4.y + v4.z + v4.w;
                *(float4*)&row[cidx] = v4;
            }
            sum += __shfl_xor_sync(0xffffffffu, sum, 1);
            sum += __shfl_xor_sync(0xffffffffu, sum, 2);
            if (sub == 0) s_binv[r] = 1.f / sum;
        }
        __syncthreads();

        // ---- A*V ----
        {
            int npair = (warp >> 2) * 2;
            float cacc[2][4] = {{0.f,0.f,0.f,0.f},{0.f,0.f,0.f,0.f}};
            for (int kt = 0; kt < 43; kt++) {
                int k8 = kt * 8 + qd;
                float pa[4];
                pa[0] = to_tf32(Ssm[r0 * SSTR + k8]);
                pa[1] = to_tf32(Ssm[r1 * SSTR + k8]);
                pa[2] = to_tf32(Ssm[r0 * SSTR + k8 + 4]);
                pa[3] = to_tf32(Ssm[r1 * SSTR + k8 + 4]);
                #pragma unroll
                for (int p = 0; p < 2; p++) {
                    int n0 = (npair + p) * 8;
                    float b0 = Vs[(n0 + gid) * VSTR + k8];
                    float b1 = Vs[(n0 + gid) * VSTR + k8 + 4];
                    mma_tf32(cacc[p], pa, b0, b1);
                }
            }
            int tA2 = t0 + r0, tB2 = t0 + r1;
            float scA = s_binv[r0], scB = s_binv[r1];
            #pragma unroll
            for (int p = 0; p < 2; p++) {
                int col = (npair + p) * 8 + 2 * qd;
                if (tA2 < NTOK)
                    *(float2*)&g_ao[((size_t)b * NTOK + tA2) * DIMC + h * HD + col] =
                        make_float2(cacc[p][0] * scA, cacc[p][1] * scA);
                if (tB2 < NTOK)
                    *(float2*)&g_ao[((size_t)b * NTOK + tB2) * DIMC + h * HD + col] =
                        make_float2(cacc[p][2] * scB, cacc[p][3] * scB);
            }
        }
        __syncthreads();
    }
}

// ---------------------------------------------------------------------------
// Kernel 4: tf32-MMA projection GEMM [MROWS x 192] @ [192 x 192] (+bias)
// ---------------------------------------------------------------------------
__global__ __launch_bounds__(256) void proj_gemm_tc(const float* __restrict__ W,
                                                    const float* __restrict__ bias,
                                                    float* __restrict__ out)
{
    __shared__ float As[128 * GSTR];
    __shared__ float Bs[64 * GSTR];
    int tid = threadIdx.x, lane = tid & 31, warp = tid >> 5;
    int gid = lane >> 2, qd = lane & 3;
    int m0 = blockIdx.y * 128, n0 = blockIdx.x * 64;
    int mrow = (warp & 3) * 32, ncol = (warp >> 2) * 32;
    int arow = tid >> 1, ac0 = (tid & 1) * 16;
    int brow = tid >> 2, bc0 = (tid & 3) * 8;

    float c[2][4][4];
    #pragma unroll
    for (int mt = 0; mt < 2; mt++)
        #pragma unroll
        for (int nt = 0; nt < 4; nt++)
            #pragma unroll
            for (int i = 0; i < 4; i++) c[mt][nt][i] = 0.f;

    for (int k0 = 0; k0 < DIMC; k0 += 32) {
        #pragma unroll
        for (int i = 0; i < 4; i++) {
            float4 v = *(const float4*)&g_ao[(size_t)(m0 + arow) * DIMC + k0 + ac0 + i * 4];
            v.x = to_tf32(v.x); v.y = to_tf32(v.y); v.z = to_tf32(v.z); v.w = to_tf32(v.w);
            *(float4*)&As[arow * GSTR + ac0 + i * 4] = v;
        }
        #pragma unroll
        for (int i = 0; i < 2; i++) {
            float4 v = *(const float4*)&W[(size_t)(n0 + brow) * DIMC + k0 + bc0 + i * 4];
            v.x = to_tf32(v.x); v.y = to_tf32(v.y); v.z = to_tf32(v.z); v.w = to_tf32(v.w);
            *(float4*)&Bs[brow * GSTR + bc0 + i * 4] = v;
        }
        __syncthreads();
        #pragma unroll
        for (int k8 = 0; k8 < 4; k8++) {
            int kk = k8 * 8;
            float a[2][4], b[4][2];
            #pragma unroll
            for (int mt = 0; mt < 2; mt++) {
                int r = mrow + mt * 16 + gid;
                a[mt][0] = As[r * GSTR + kk + qd];
                a[mt][1] = As[(r + 8) * GSTR + kk + qd];
                a[mt][2] = As[r * GSTR + kk + qd + 4];
                a[mt][3] = As[(r + 8) * GSTR + kk + qd + 4];
            }
            #pragma unroll
            for (int nt = 0; nt < 4; nt++) {
                int rn = ncol + nt * 8 + gid;
                b[nt][0] = Bs[rn * GSTR + kk + qd];
                b[nt][1] = Bs[rn * GSTR + kk + qd + 4];
            }
            #pragma unroll
            for (int mt = 0; mt < 2; mt++)
                #pragma unroll
                for (int nt = 0; nt < 4; nt++)
                    mma_tf32(c[mt][nt], a[mt], b[nt][0], b[nt][1]);
        }
        __syncthreads();
    }

    #pragma unroll
    for (int mt = 0; mt < 2; mt++) {
        int gmA = m0 + mrow + mt * 16 + gid, gmB = gmA + 8;
        #pragma unroll
        for (int nt = 0; nt < 4; nt++) {
            int gn = n0 + ncol + nt * 8 + 2 * qd;
            float b0 = bias[gn], b1 = bias[gn + 1];
            *(float2*)&out[(size_t)gmA * DIMC + gn] =
                make_float2(c[mt][nt][0] + b0, c[mt][nt][1] + b1);
            *(float2*)&out[(size_t)gmB * DIMC + gn] =
                make_float2(c[mt][nt][2] + b0, c[mt][nt][3] + b1);
        }
    }
}

// ---------------------------------------------------------------------------
extern "C" void kernel_launch(void* const* d_in, const int* in_sizes, int n_in,
                              void* d_out, int out_size)
{
    const float* x      = (const float*)d_in[0];
    const float* mask   = (const float*)d_in[1];
    const float* qkv_w  = (const float*)d_in[2];
    const float* qkv_b  = (const float*)d_in[3];
    const float* rpb    = (const float*)d_in[4];
    const float* proj_w = (const float*)d_in[5];
    const float* proj_b = (const float*)d_in[6];
    float* out = (float*)d_out;

    (void)in_sizes; (void)n_in; (void)out_size;

    int smem = (344 * KSTR + 32 * VSTR + 64 * QSTR + 64 * SSTR) * (int)sizeof(float);
    cudaFuncSetAttribute(attn_tc, cudaFuncAttributeMaxDynamicSharedMemorySize, smem);

    bm_kernel<<<dim3(NTOK, NWIN * NHEADS), 128>>>(rpb, mask);
    qkv_gemm_tc<<<dim3(QKVN / 64, MROWS / 128), 256>>>(x, qkv_w, qkv_b);
    attn_tc<<<dim3(NHEADS, NB), 256, smem>>>(mask);
    proj_gemm_tc<<<dim3(DIMC / 64, MROWS / 128), 256>>>(proj_w, proj_b, out);
}

// round 6
// speedup vs baseline: 2.4947x; 1.1463x over previous
#include <cuda_runtime.h>
#include <math.h>

#define NHEADS 6
#define NTOK   343
#define DIMC   192
#define HD     32
#define NB     256
#define NWIN   64
#define MROWS  (NB*NTOK)      // 87808
#define QKVN   576
#define SCALEF 0.17677669529663687f

// attn smem strides: %32==8 -> conflict-free float2/scalar fragment access
#define KSTR 40   // K rows [key][hd-permuted]
#define QSTR 40   // Q rows [q][hd-permuted]
#define VSTR 40   // V rows [key][hd]  (B operand read by row=key)
#define SSTR 360  // S strip [q][key-permuted]
#define GSTR 36   // gemm smem stride (unchanged, scalar frag loads)

// ---- scratch (device globals; no runtime allocation) ----
__device__ float g_q[(size_t)NB*NHEADS*NTOK*HD];
__device__ float g_k[(size_t)NB*NHEADS*NTOK*HD];
__device__ float g_v[(size_t)NB*NHEADS*NTOK*HD];
__device__ float g_bm[(size_t)NWIN*NHEADS*NTOK*344];   // bias+mask, key-permuted cols
__device__ float g_ao[(size_t)NB*NTOK*DIMC];

__device__ __forceinline__ float to_tf32(float x) {
    float r;
    asm("cvt.rna.tf32.f32 %0, %1;" : "=f"(r) : "f"(x));
    return r;
}

// permute within 8-group: (c,c+4) frag pairs become adjacent (2c', 2c'+1)
__device__ __forceinline__ int perm8(int c) {
    return (c & ~7) | ((c & 3) << 1) | ((c >> 2) & 1);
}

__device__ __forceinline__ void mma_tf32(float* c, const float* a, float b0f, float b1f) {
    unsigned A0 = __float_as_uint(a[0]), A1 = __float_as_uint(a[1]);
    unsigned A2 = __float_as_uint(a[2]), A3 = __float_as_uint(a[3]);
    unsigned B0 = __float_as_uint(b0f),  B1 = __float_as_uint(b1f);
    asm volatile(
        "mma.sync.aligned.m16n8k8.row.col.f32.tf32.tf32.f32 "
        "{%0,%1,%2,%3}, {%4,%5,%6,%7}, {%8,%9}, {%0,%1,%2,%3};"
        : "+f"(c[0]), "+f"(c[1]), "+f"(c[2]), "+f"(c[3])
        : "r"(A0), "r"(A1), "r"(A2), "r"(A3), "r"(B0), "r"(B1));
}

// ---------------------------------------------------------------------------
// Kernel 1: fuse rpb gather + mask into g_bm[(w*6+h)][i][perm8(j)]
// ---------------------------------------------------------------------------
__global__ void bm_kernel(const float* __restrict__ rpb, const float* __restrict__ mask)
{
    int i  = blockIdx.x;          // 0..342
    int wh = blockIdx.y;          // w*6+h
    int w  = wh / NHEADS, h = wh - w * NHEADS;
    int di = i / 49, hi = (i / 7) % 7, wi = i % 7;
    float* dst = g_bm + ((size_t)wh * NTOK + i) * 344;
    const float* mrow = mask + ((size_t)w * NTOK + i) * NTOK;
    for (int j = threadIdx.x; j < 344; j += 128) {
        float val = 0.f;
        if (j < NTOK) {
            int dj = j / 49, hj = (j / 7) % 7, wj = j % 7;
            int idx = (di - dj + 6) * 169 + (hi - hj + 6) * 13 + (wi - wj + 6);
            val = rpb[idx * NHEADS + h] + mrow[j];
        }
        dst[perm8(j)] = val;
    }
}

// ---------------------------------------------------------------------------
// Kernel 2: tf32-MMA QKV GEMM [MROWS x 192] @ W^T[192 x 576] (+bias), scatter
// ---------------------------------------------------------------------------
__global__ __launch_bounds__(256) void qkv_gemm_tc(const float* __restrict__ X,
                                                   const float* __restrict__ W,
                                                   const float* __restrict__ bias)
{
    __shared__ float As[128 * GSTR];
    __shared__ float Bs[64 * GSTR];
    int tid = threadIdx.x, lane = tid & 31, warp = tid >> 5;
    int gid = lane >> 2, qd = lane & 3;
    int m0 = blockIdx.y * 128, n0 = blockIdx.x * 64;
    int mrow = (warp & 3) * 32, ncol = (warp >> 2) * 32;
    int arow = tid >> 1, ac0 = (tid & 1) * 16;
    int brow = tid >> 2, bc0 = (tid & 3) * 8;

    float c[2][4][4];
    #pragma unroll
    for (int mt = 0; mt < 2; mt++)
        #pragma unroll
        for (int nt = 0; nt < 4; nt++)
            #pragma unroll
            for (int i = 0; i < 4; i++) c[mt][nt][i] = 0.f;

    for (int k0 = 0; k0 < DIMC; k0 += 32) {
        #pragma unroll
        for (int i = 0; i < 4; i++) {
            float4 v = *(const float4*)&X[(size_t)(m0 + arow) * DIMC + k0 + ac0 + i * 4];
            v.x = to_tf32(v.x); v.y = to_tf32(v.y); v.z = to_tf32(v.z); v.w = to_tf32(v.w);
            *(float4*)&As[arow * GSTR + ac0 + i * 4] = v;
        }
        #pragma unroll
        for (int i = 0; i < 2; i++) {
            float4 v = *(const float4*)&W[(size_t)(n0 + brow) * DIMC + k0 + bc0 + i * 4];
            v.x = to_tf32(v.x); v.y = to_tf32(v.y); v.z = to_tf32(v.z); v.w = to_tf32(v.w);
            *(float4*)&Bs[brow * GSTR + bc0 + i * 4] = v;
        }
        __syncthreads();
        #pragma unroll
        for (int k8 = 0; k8 < 4; k8++) {
            int kk = k8 * 8;
            float a[2][4], b[4][2];
            #pragma unroll
            for (int mt = 0; mt < 2; mt++) {
                int r = mrow + mt * 16 + gid;
                a[mt][0] = As[r * GSTR + kk + qd];
                a[mt][1] = As[(r + 8) * GSTR + kk + qd];
                a[mt][2] = As[r * GSTR + kk + qd + 4];
                a[mt][3] = As[(r + 8) * GSTR + kk + qd + 4];
            }
            #pragma unroll
            for (int nt = 0; nt < 4; nt++) {
                int rn = ncol + nt * 8 + gid;
                b[nt][0] = Bs[rn * GSTR + kk + qd];
                b[nt][1] = Bs[rn * GSTR + kk + qd + 4];
            }
            #pragma unroll
            for (int mt = 0; mt < 2; mt++)
                #pragma unroll
                for (int nt = 0; nt < 4; nt++)
                    mma_tf32(c[mt][nt], a[mt], b[nt][0], b[nt][1]);
        }
        __syncthreads();
    }

    #pragma unroll
    for (int mt = 0; mt < 2; mt++) {
        int gmA = m0 + mrow + mt * 16 + gid, gmB = gmA + 8;
        int bA = gmA / NTOK, tA = gmA - bA * NTOK;
        int bB = gmB / NTOK, tB = gmB - bB * NTOK;
        #pragma unroll
        for (int nt = 0; nt < 4; nt++) {
            int gn = n0 + ncol + nt * 8 + 2 * qd;
            int sec = gn / DIMC, rem = gn - sec * DIMC;
            int hh = rem >> 5, dd = rem & 31;
            float b0 = bias[gn], b1 = bias[gn + 1];
            float vA0 = c[mt][nt][0] + b0, vA1 = c[mt][nt][1] + b1;
            float vB0 = c[mt][nt][2] + b0, vB1 = c[mt][nt][3] + b1;
            size_t offA = (((size_t)bA * NHEADS + hh) * NTOK + tA) * HD + dd;
            size_t offB = (((size_t)bB * NHEADS + hh) * NTOK + tB) * HD + dd;
            if (sec == 0) {
                *(float2*)&g_q[offA] = make_float2(to_tf32(vA0 * SCALEF), to_tf32(vA1 * SCALEF));
                *(float2*)&g_q[offB] = make_float2(to_tf32(vB0 * SCALEF), to_tf32(vB1 * SCALEF));
            } else if (sec == 1) {
                *(float2*)&g_k[offA] = make_float2(to_tf32(vA0), to_tf32(vA1));
                *(float2*)&g_k[offB] = make_float2(to_tf32(vB0), to_tf32(vB1));
            } else {
                *(float2*)&g_v[offA] = make_float2(to_tf32(vA0), to_tf32(vA1));
                *(float2*)&g_v[offB] = make_float2(to_tf32(vB0), to_tf32(vB1));
            }
        }
    }
}

// ---------------------------------------------------------------------------
// Kernel 3: tensor-core attention, 512 threads, permuted-vectorized fragments
// ---------------------------------------------------------------------------
__global__ __launch_bounds__(512) void attn_tc()
{
    extern __shared__ float sm[];
    float* Ks  = sm;                       // 344*40  [key][hd-perm]
    float* Vs  = Ks + 344 * KSTR;          // 344*40  [key][hd]
    float* Qs  = Vs + 344 * VSTR;          // 64*40   [q][hd-perm]
    float* Ssm = Qs + 64 * QSTR;           // 64*360  [q][key-perm]
    __shared__ float s_binv[64];

    int tid  = threadIdx.x;
    int h    = blockIdx.x;
    int b    = blockIdx.y;
    int w    = b & (NWIN - 1);
    int lane = tid & 31, warp = tid >> 5;
    int gid  = lane >> 2, qd = lane & 3;
    int wsub = warp >> 2;                  // 0..3

    size_t base = (((size_t)b * NHEADS) + h) * NTOK * HD;
    const float* qg = g_q + base;
    const float* kg = g_k + base;
    const float* vg = g_v + base;
    const float* bm = g_bm + (size_t)(w * NHEADS + h) * NTOK * 344;

    for (int i = tid; i < 344 * 32; i += 512) {
        int j = i >> 5, d = i & 31;
        float kv = 0.f, vv = 0.f;
        if (j < NTOK) { kv = kg[i]; vv = vg[i]; }
        Ks[j * KSTR + perm8(d)] = kv;
        Vs[j * VSTR + d] = vv;
    }
    __syncthreads();

    int mrow = (warp & 3) * 16;
    int r0 = mrow + gid, r1 = r0 + 8;
    // permuted in-group offsets for QK epilogue stores (key-perm of 2qd, 2qd+1)
    int e0 = ((2 * qd & 3) << 1) | ((2 * qd >> 2) & 1);
    int e1 = (((2 * qd + 1) & 3) << 1) | (((2 * qd + 1) >> 2) & 1);

    for (int it = 0; it < 6; it++) {
        int t0 = it * 64;

        for (int i = tid; i < 64 * 32; i += 512) {
            int r = i >> 5, d = i & 31;
            int t = t0 + r; if (t > NTOK - 1) t = NTOK - 1;
            Qs[r * QSTR + perm8(d)] = qg[t * HD + d];
        }
        __syncthreads();

        // ---- QK^T : raw scores into Ssm (key-permuted cols) ----
        float a[4][4];
        #pragma unroll
        for (int ks = 0; ks < 4; ks++) {
            int kk = ks * 8 + 2 * qd;
            float2 a0 = *(const float2*)&Qs[r0 * QSTR + kk];
            float2 a1 = *(const float2*)&Qs[r1 * QSTR + kk];
            a[ks][0] = a0.x; a[ks][2] = a0.y;
            a[ks][1] = a1.x; a[ks][3] = a1.y;
        }
        for (int nt = wsub; nt < 43; nt += 4) {
            int n0 = nt * 8;
            float c[4] = {0.f, 0.f, 0.f, 0.f};
            #pragma unroll
            for (int ks = 0; ks < 4; ks++) {
                float2 b2 = *(const float2*)&Ks[(n0 + gid) * KSTR + ks * 8 + 2 * qd];
                mma_tf32(c, a[ks], b2.x, b2.y);
            }
            int j0 = n0 + 2 * qd, j1 = j0 + 1;
            Ssm[r0 * SSTR + n0 + e0] = (j0 < NTOK) ? c[0] : -1e30f;
            Ssm[r0 * SSTR + n0 + e1] = (j1 < NTOK) ? c[1] : -1e30f;
            Ssm[r1 * SSTR + n0 + e0] = (j0 < NTOK) ? c[2] : -1e30f;
            Ssm[r1 * SSTR + n0 + e1] = (j1 < NTOK) ? c[3] : -1e30f;
        }
        __syncthreads();

        // ---- row softmax: add bm (same permuted layout) + max/exp/sum ----
        {
            int r = tid >> 3, sub = tid & 7;
            int t = t0 + r; if (t > NTOK - 1) t = NTOK - 1;
            float* row = Ssm + r * SSTR;
            const float* bmr = bm + (size_t)t * 344;
            float mx = -1e30f;
            for (int cidx = sub * 4; cidx < 344; cidx += 32) {
                float4 v4 = *(const float4*)&row[cidx];
                float4 b4 = *(const float4*)&bmr[cidx];
                v4.x += b4.x; v4.y += b4.y; v4.z += b4.z; v4.w += b4.w;
                *(float4*)&row[cidx] = v4;
                mx = fmaxf(mx, fmaxf(fmaxf(v4.x, v4.y), fmaxf(v4.z, v4.w)));
            }
            mx = fmaxf(mx, __shfl_xor_sync(0xffffffffu, mx, 1));
            mx = fmaxf(mx, __shfl_xor_sync(0xffffffffu, mx, 2));
            mx = fmaxf(mx, __shfl_xor_sync(0xffffffffu, mx, 4));
            float sum = 0.f;
            for (int cidx = sub * 4; cidx < 344; cidx += 32) {
                float4 v4 = *(const float4*)&row[cidx];
                v4.x = __expf(v4.x - mx); v4.y = __expf(v4.y - mx);
                v4.z = __expf(v4.z - mx); v4.w = __expf(v4.w - mx);
                sum += v4.x + v4.y + v4.z + v4.w;
                *(float4*)&row[cidx] = v4;
            }
            sum += __shfl_xor_sync(0xffffffffu, sum, 1);
            sum += __shfl_xor_sync(0xffffffffu, sum, 2);
            sum += __shfl_xor_sync(0xffffffffu, sum, 4);
            if (sub == 0) s_binv[r] = 1.f / sum;
        }
        __syncthreads();

        // ---- A*V : each warp one 8-col hd tile ----
        {
            int n0 = wsub * 8;
            float cacc[4] = {0.f, 0.f, 0.f, 0.f};
            for (int kt = 0; kt < 43; kt++) {
                int kk = kt * 8 + 2 * qd;
                float2 pA = *(const float2*)&Ssm[r0 * SSTR + kk];
                float2 pB = *(const float2*)&Ssm[r1 * SSTR + kk];
                float pa[4];
                pa[0] = to_tf32(pA.x); pa[1] = to_tf32(pB.x);
                pa[2] = to_tf32(pA.y); pa[3] = to_tf32(pB.y);
                float b0 = Vs[(kt * 8 + qd) * VSTR + n0 + gid];
                float b1 = Vs[(kt * 8 + qd + 4) * VSTR + n0 + gid];
                mma_tf32(cacc, pa, b0, b1);
            }
            int tA2 = t0 + r0, tB2 = t0 + r1;
            float scA = s_binv[r0], scB = s_binv[r1];
            int col = n0 + 2 * qd;
            if (tA2 < NTOK)
                *(float2*)&g_ao[((size_t)b * NTOK + tA2) * DIMC + h * HD + col] =
                    make_float2(cacc[0] * scA, cacc[1] * scA);
            if (tB2 < NTOK)
                *(float2*)&g_ao[((size_t)b * NTOK + tB2) * DIMC + h * HD + col] =
                    make_float2(cacc[2] * scB, cacc[3] * scB);
        }
        __syncthreads();
    }
}

// ---------------------------------------------------------------------------
// Kernel 4: tf32-MMA projection GEMM [MROWS x 192] @ [192 x 192] (+bias)
// ---------------------------------------------------------------------------
__global__ __launch_bounds__(256) void proj_gemm_tc(const float* __restrict__ W,
                                                    const float* __restrict__ bias,
                                                    float* __restrict__ out)
{
    __shared__ float As[128 * GSTR];
    __shared__ float Bs[64 * GSTR];
    int tid = threadIdx.x, lane = tid & 31, warp = tid >> 5;
    int gid = lane >> 2, qd = lane & 3;
    int m0 = blockIdx.y * 128, n0 = blockIdx.x * 64;
    int mrow = (warp & 3) * 32, ncol = (warp >> 2) * 32;
    int arow = tid >> 1, ac0 = (tid & 1) * 16;
    int brow = tid >> 2, bc0 = (tid & 3) * 8;

    float c[2][4][4];
    #pragma unroll
    for (int mt = 0; mt < 2; mt++)
        #pragma unroll
        for (int nt = 0; nt < 4; nt++)
            #pragma unroll
            for (int i = 0; i < 4; i++) c[mt][nt][i] = 0.f;

    for (int k0 = 0; k0 < DIMC; k0 += 32) {
        #pragma unroll
        for (int i = 0; i < 4; i++) {
            float4 v = *(const float4*)&g_ao[(size_t)(m0 + arow) * DIMC + k0 + ac0 + i * 4];
            v.x = to_tf32(v.x); v.y = to_tf32(v.y); v.z = to_tf32(v.z); v.w = to_tf32(v.w);
            *(float4*)&As[arow * GSTR + ac0 + i * 4] = v;
        }
        #pragma unroll
        for (int i = 0; i < 2; i++) {
            float4 v = *(const float4*)&W[(size_t)(n0 + brow) * DIMC + k0 + bc0 + i * 4];
            v.x = to_tf32(v.x); v.y = to_tf32(v.y); v.z = to_tf32(v.z); v.w = to_tf32(v.w);
            *(float4*)&Bs[brow * GSTR + bc0 + i * 4] = v;
        }
        __syncthreads();
        #pragma unroll
        for (int k8 = 0; k8 < 4; k8++) {
            int kk = k8 * 8;
            float a[2][4], b[4][2];
            #pragma unroll
            for (int mt = 0; mt < 2; mt++) {
                int r = mrow + mt * 16 + gid;
                a[mt][0] = As[r * GSTR + kk + qd];
                a[mt][1] = As[(r + 8) * GSTR + kk + qd];
                a[mt][2] = As[r * GSTR + kk + qd + 4];
                a[mt][3] = As[(r + 8) * GSTR + kk + qd + 4];
            }
            #pragma unroll
            for (int nt = 0; nt < 4; nt++) {
                int rn = ncol + nt * 8 + gid;
                b[nt][0] = Bs[rn * GSTR + kk + qd];
                b[nt][1] = Bs[rn * GSTR + kk + qd + 4];
            }
            #pragma unroll
            for (int mt = 0; mt < 2; mt++)
                #pragma unroll
                for (int nt = 0; nt < 4; nt++)
                    mma_tf32(c[mt][nt], a[mt], b[nt][0], b[nt][1]);
        }
        __syncthreads();
    }

    #pragma unroll
    for (int mt = 0; mt < 2; mt++) {
        int gmA = m0 + mrow + mt * 16 + gid, gmB = gmA + 8;
        #pragma unroll
        for (int nt = 0; nt < 4; nt++) {
            int gn = n0 + ncol + nt * 8 + 2 * qd;
            float b0 = bias[gn], b1 = bias[gn + 1];
            *(float2*)&out[(size_t)gmA * DIMC + gn] =
                make_float2(c[mt][nt][0] + b0, c[mt][nt][1] + b1);
            *(float2*)&out[(size_t)gmB * DIMC + gn] =
                make_float2(c[mt][nt][2] + b0, c[mt][nt][3] + b1);
        }
    }
}

// ---------------------------------------------------------------------------
extern "C" void kernel_launch(void* const* d_in, const int* in_sizes, int n_in,
                              void* d_out, int out_size)
{
    const float* x      = (const float*)d_in[0];
    const float* mask   = (const float*)d_in[1];
    const float* qkv_w  = (const float*)d_in[2];
    const float* qkv_b  = (const float*)d_in[3];
    const float* rpb    = (const float*)d_in[4];
    const float* proj_w = (const float*)d_in[5];
    const float* proj_b = (const float*)d_in[6];
    float* out = (float*)d_out;

    (void)in_sizes; (void)n_in; (void)out_size;

    int smem = (344 * KSTR + 344 * VSTR + 64 * QSTR + 64 * SSTR) * (int)sizeof(float);
    cudaFuncSetAttribute(attn_tc, cudaFuncAttributeMaxDynamicSharedMemorySize, smem);

    bm_kernel<<<dim3(NTOK, NWIN * NHEADS), 128>>>(rpb, mask);
    qkv_gemm_tc<<<dim3(QKVN / 64, MROWS / 128), 256>>>(x, qkv_w, qkv_b);
    attn_tc<<<dim3(NHEADS, NB), 512, smem>>>();
    proj_gemm_tc<<<dim3(DIMC / 64, MROWS / 128), 256>>>(proj_w, proj_b, out);
}

// round 8
// speedup vs baseline: 2.9708x; 1.1908x over previous
#include <cuda_runtime.h>
#include <math.h>

#define NHEADS 6
#define NTOK   343
#define DIMC   192
#define HD     32
#define NB     256
#define NWIN   64
#define MROWS  (NB*NTOK)      // 87808
#define QKVN   576
#define SCALEF 0.17677669529663687f

#define KSTR 40   // K rows [key][hd-perm]   (%32==8)
#define QSTR 40   // Q rows [q][hd-perm]
#define VSTR 36   // V rows [key][hd]        (%32==4 -> paired-row loads conflict-free)
#define GSTR 36   // gemm smem stride

// ---- scratch (device globals; no runtime allocation) ----
__device__ float g_q[(size_t)NB*NHEADS*NTOK*HD];
__device__ float g_k[(size_t)NB*NHEADS*NTOK*HD];
__device__ float g_v[(size_t)NB*NHEADS*NTOK*HD];
__device__ float g_bm[(size_t)NWIN*NHEADS*NTOK*344];   // bias+mask, natural cols
__device__ float g_ao[(size_t)NB*NTOK*DIMC];

__device__ __forceinline__ float to_tf32(float x) {
    float r;
    asm("cvt.rna.tf32.f32 %0, %1;" : "=f"(r) : "f"(x));
    return r;
}

// permute within 8-group: (c,c+4) frag pairs become adjacent (2c', 2c'+1)
__device__ __forceinline__ int perm8(int c) {
    return (c & ~7) | ((c & 3) << 1) | ((c >> 2) & 1);
}

__device__ __forceinline__ void mma_tf32(float* c, const float* a, float b0f, float b1f) {
    unsigned A0 = __float_as_uint(a[0]), A1 = __float_as_uint(a[1]);
    unsigned A2 = __float_as_uint(a[2]), A3 = __float_as_uint(a[3]);
    unsigned B0 = __float_as_uint(b0f),  B1 = __float_as_uint(b1f);
    asm volatile(
        "mma.sync.aligned.m16n8k8.row.col.f32.tf32.tf32.f32 "
        "{%0,%1,%2,%3}, {%4,%5,%6,%7}, {%8,%9}, {%0,%1,%2,%3};"
        : "+f"(c[0]), "+f"(c[1]), "+f"(c[2]), "+f"(c[3])
        : "r"(A0), "r"(A1), "r"(A2), "r"(A3), "r"(B0), "r"(B1));
}

// ---------------------------------------------------------------------------
// Kernel 1: fuse rpb gather + mask into g_bm[(w*6+h)][i][j] (natural order)
// ---------------------------------------------------------------------------
__global__ void bm_kernel(const float* __restrict__ rpb, const float* __restrict__ mask)
{
    int i  = blockIdx.x;          // 0..342
    int wh = blockIdx.y;          // w*6+h
    int w  = wh / NHEADS, h = wh - w * NHEADS;
    int di = i / 49, hi = (i / 7) % 7, wi = i % 7;
    float* dst = g_bm + ((size_t)wh * NTOK + i) * 344;
    const float* mrow = mask + ((size_t)w * NTOK + i) * NTOK;
    for (int j = threadIdx.x; j < 344; j += 128) {
        float val = 0.f;
        if (j < NTOK) {
            int dj = j / 49, hj = (j / 7) % 7, wj = j % 7;
            int idx = (di - dj + 6) * 169 + (hi - hj + 6) * 13 + (wi - wj + 6);
            val = rpb[idx * NHEADS + h] + mrow[j];
        }
        dst[j] = val;
    }
}

// ---------------------------------------------------------------------------
// Kernel 2: tf32-MMA QKV GEMM [MROWS x 192] @ W^T[192 x 576] (+bias), scatter
// ---------------------------------------------------------------------------
__global__ __launch_bounds__(256) void qkv_gemm_tc(const float* __restrict__ X,
                                                   const float* __restrict__ W,
                                                   const float* __restrict__ bias)
{
    __shared__ float As[128 * GSTR];
    __shared__ float Bs[64 * GSTR];
    int tid = threadIdx.x, lane = tid & 31, warp = tid >> 5;
    int gid = lane >> 2, qd = lane & 3;
    int m0 = blockIdx.y * 128, n0 = blockIdx.x * 64;
    int mrow = (warp & 3) * 32, ncol = (warp >> 2) * 32;
    int arow = tid >> 1, ac0 = (tid & 1) * 16;
    int brow = tid >> 2, bc0 = (tid & 3) * 8;

    float c[2][4][4];
    #pragma unroll
    for (int mt = 0; mt < 2; mt++)
        #pragma unroll
        for (int nt = 0; nt < 4; nt++)
            #pragma unroll
            for (int i = 0; i < 4; i++) c[mt][nt][i] = 0.f;

    for (int k0 = 0; k0 < DIMC; k0 += 32) {
        #pragma unroll
        for (int i = 0; i < 4; i++) {
            float4 v = *(const float4*)&X[(size_t)(m0 + arow) * DIMC + k0 + ac0 + i * 4];
            v.x = to_tf32(v.x); v.y = to_tf32(v.y); v.z = to_tf32(v.z); v.w = to_tf32(v.w);
            *(float4*)&As[arow * GSTR + ac0 + i * 4] = v;
        }
        #pragma unroll
        for (int i = 0; i < 2; i++) {
            float4 v = *(const float4*)&W[(size_t)(n0 + brow) * DIMC + k0 + bc0 + i * 4];
            v.x = to_tf32(v.x); v.y = to_tf32(v.y); v.z = to_tf32(v.z); v.w = to_tf32(v.w);
            *(float4*)&Bs[brow * GSTR + bc0 + i * 4] = v;
        }
        __syncthreads();
        #pragma unroll
        for (int k8 = 0; k8 < 4; k8++) {
            int kk = k8 * 8;
            float a[2][4], b[4][2];
            #pragma unroll
            for (int mt = 0; mt < 2; mt++) {
                int r = mrow + mt * 16 + gid;
                a[mt][0] = As[r * GSTR + kk + qd];
                a[mt][1] = As[(r + 8) * GSTR + kk + qd];
                a[mt][2] = As[r * GSTR + kk + qd + 4];
                a[mt][3] = As[(r + 8) * GSTR + kk + qd + 4];
            }
            #pragma unroll
            for (int nt = 0; nt < 4; nt++) {
                int rn = ncol + nt * 8 + gid;
                b[nt][0] = Bs[rn * GSTR + kk + qd];
                b[nt][1] = Bs[rn * GSTR + kk + qd + 4];
            }
            #pragma unroll
            for (int mt = 0; mt < 2; mt++)
                #pragma unroll
                for (int nt = 0; nt < 4; nt++)
                    mma_tf32(c[mt][nt], a[mt], b[nt][0], b[nt][1]);
        }
        __syncthreads();
    }

    #pragma unroll
    for (int mt = 0; mt < 2; mt++) {
        int gmA = m0 + mrow + mt * 16 + gid, gmB = gmA + 8;
        int bA = gmA / NTOK, tA = gmA - bA * NTOK;
        int bB = gmB / NTOK, tB = gmB - bB * NTOK;
        #pragma unroll
        for (int nt = 0; nt < 4; nt++) {
            int gn = n0 + ncol + nt * 8 + 2 * qd;
            int sec = gn / DIMC, rem = gn - sec * DIMC;
            int hh = rem >> 5, dd = rem & 31;
            float b0 = bias[gn], b1 = bias[gn + 1];
            float vA0 = c[mt][nt][0] + b0, vA1 = c[mt][nt][1] + b1;
            float vB0 = c[mt][nt][2] + b0, vB1 = c[mt][nt][3] + b1;
            size_t offA = (((size_t)bA * NHEADS + hh) * NTOK + tA) * HD + dd;
            size_t offB = (((size_t)bB * NHEADS + hh) * NTOK + tB) * HD + dd;
            if (sec == 0) {
                *(float2*)&g_q[offA] = make_float2(to_tf32(vA0 * SCALEF), to_tf32(vA1 * SCALEF));
                *(float2*)&g_q[offB] = make_float2(to_tf32(vB0 * SCALEF), to_tf32(vB1 * SCALEF));
            } else if (sec == 1) {
                *(float2*)&g_k[offA] = make_float2(to_tf32(vA0), to_tf32(vA1));
                *(float2*)&g_k[offB] = make_float2(to_tf32(vB0), to_tf32(vB1));
            } else {
                *(float2*)&g_v[offA] = make_float2(to_tf32(vA0), to_tf32(vA1));
                *(float2*)&g_v[offB] = make_float2(to_tf32(vB0), to_tf32(vB1));
            }
        }
    }
}

// ---------------------------------------------------------------------------
// Kernel 3: register-resident flash attention. One block per (head, window).
// Each warp owns 16-query tiles independently; P never touches smem;
// online softmax; no __syncthreads in the main loop.
// ---------------------------------------------------------------------------
struct WarpState {
    float a[4][4];       // Q frags (4 k-tiles)
    float occ[4][4];     // O accum (4 hd-tiles)
    float m0, m1, s0, s1;
};

template<int CN>
__device__ __forceinline__ void attn_chunk(int ct, int gid, int qd,
                                           const float* __restrict__ Ks,
                                           const float* __restrict__ Vs,
                                           const float* __restrict__ bmA,
                                           const float* __restrict__ bmB,
                                           WarpState& st)
{
    float p[CN][4];
    float cm0 = -1e30f, cm1 = -1e30f;
    #pragma unroll
    for (int t = 0; t < CN; t++) {
        int n0 = (ct + t) * 8;
        float c[4] = {0.f, 0.f, 0.f, 0.f};
        #pragma unroll
        for (int ks = 0; ks < 4; ks++) {
            float2 b2 = *(const float2*)&Ks[(n0 + gid) * KSTR + ks * 8 + 2 * qd];
            mma_tf32(c, st.a[ks], b2.x, b2.y);
        }
        float2 mA = *(const float2*)&bmA[n0 + 2 * qd];
        float2 mB = *(const float2*)&bmB[n0 + 2 * qd];
        c[0] += mA.x; c[1] += mA.y; c[2] += mB.x; c[3] += mB.y;
        if (n0 + 2 * qd >= NTOK)     { c[0] = -1e30f; c[2] = -1e30f; }
        if (n0 + 2 * qd + 1 >= NTOK) { c[1] = -1e30f; c[3] = -1e30f; }
        p[t][0] = c[0]; p[t][1] = c[1]; p[t][2] = c[2]; p[t][3] = c[3];
        cm0 = fmaxf(cm0, fmaxf(c[0], c[1]));
        cm1 = fmaxf(cm1, fmaxf(c[2], c[3]));
    }
    cm0 = fmaxf(cm0, __shfl_xor_sync(0xffffffffu, cm0, 1));
    cm0 = fmaxf(cm0, __shfl_xor_sync(0xffffffffu, cm0, 2));
    cm1 = fmaxf(cm1, __shfl_xor_sync(0xffffffffu, cm1, 1));
    cm1 = fmaxf(cm1, __shfl_xor_sync(0xffffffffu, cm1, 2));
    float mn0 = fmaxf(st.m0, cm0), mn1 = fmaxf(st.m1, cm1);
    float sc0 = __expf(st.m0 - mn0), sc1 = __expf(st.m1 - mn1);
    st.m0 = mn0; st.m1 = mn1;
    st.s0 *= sc0; st.s1 *= sc1;
    #pragma unroll
    for (int nh = 0; nh < 4; nh++) {
        st.occ[nh][0] *= sc0; st.occ[nh][1] *= sc0;
        st.occ[nh][2] *= sc1; st.occ[nh][3] *= sc1;
    }
    #pragma unroll
    for (int t = 0; t < CN; t++) {
        float e0 = __expf(p[t][0] - st.m0);
        float e1 = __expf(p[t][1] - st.m0);
        float e2 = __expf(p[t][2] - st.m1);
        float e3 = __expf(p[t][3] - st.m1);
        st.s0 += e0 + e1; st.s1 += e2 + e3;
        float pa[4] = { to_tf32(e0), to_tf32(e2), to_tf32(e1), to_tf32(e3) };
        int n0 = (ct + t) * 8;
        const float* v0 = &Vs[(n0 + 2 * qd) * VSTR];
        const float* v1 = v0 + VSTR;
        #pragma unroll
        for (int nh = 0; nh < 4; nh++)
            mma_tf32(st.occ[nh], pa, v0[nh * 8 + gid], v1[nh * 8 + gid]);
    }
}

__global__ __launch_bounds__(512) void attn_tc()
{
    extern __shared__ float sm[];
    float* Ks = sm;                    // 344*40 [key][hd-perm]
    float* Vs = Ks + 344 * KSTR;       // 344*36 [key][hd]
    float* Qs = Vs + 344 * VSTR;       // 352*40 [q][hd-perm]

    int tid  = threadIdx.x;
    int h    = blockIdx.x;
    int b    = blockIdx.y;
    int w    = b & (NWIN - 1);
    int lane = tid & 31, warp = tid >> 5;
    int gid  = lane >> 2, qd = lane & 3;

    size_t base = (((size_t)b * NHEADS) + h) * NTOK * HD;
    const float* qg = g_q + base;
    const float* kg = g_k + base;
    const float* vg = g_v + base;
    const float* bm = g_bm + (size_t)(w * NHEADS + h) * NTOK * 344;

    for (int i = tid; i < 344 * 32; i += 512) {
        int j = i >> 5, d = i & 31;
        float kv = 0.f, vv = 0.f;
        if (j < NTOK) { kv = kg[i]; vv = vg[i]; }
        Ks[j * KSTR + perm8(d)] = kv;
        Vs[j * VSTR + d] = vv;
    }
    for (int i = tid; i < 352 * 32; i += 512) {
        int j = i >> 5, d = i & 31;
        int t = j > NTOK - 1 ? NTOK - 1 : j;
        Qs[j * QSTR + perm8(d)] = qg[t * HD + d];
    }
    __syncthreads();

    for (int wt = warp; wt < 22; wt += 16) {
        int r0 = wt * 16 + gid, r1 = r0 + 8;
        int tA = r0 > NTOK - 1 ? NTOK - 1 : r0;
        int tB = r1 > NTOK - 1 ? NTOK - 1 : r1;

        WarpState st;
        #pragma unroll
        for (int ks = 0; ks < 4; ks++) {
            float2 q0 = *(const float2*)&Qs[r0 * QSTR + ks * 8 + 2 * qd];
            float2 q1 = *(const float2*)&Qs[r1 * QSTR + ks * 8 + 2 * qd];
            st.a[ks][0] = q0.x; st.a[ks][2] = q0.y;
            st.a[ks][1] = q1.x; st.a[ks][3] = q1.y;
        }
        #pragma unroll
        for (int nh = 0; nh < 4; nh++)
            #pragma unroll
            for (int i = 0; i < 4; i++) st.occ[nh][i] = 0.f;
        st.m0 = -1e30f; st.m1 = -1e30f; st.s0 = 0.f; st.s1 = 0.f;

        const float* bmA = bm + (size_t)tA * 344;
        const float* bmB = bm + (size_t)tB * 344;

        #pragma unroll 1
        for (int ct = 0; ct < 40; ct += 4)
            attn_chunk<4>(ct, gid, qd, Ks, Vs, bmA, bmB, st);
        attn_chunk<3>(40, gid, qd, Ks, Vs, bmA, bmB, st);

        st.s0 += __shfl_xor_sync(0xffffffffu, st.s0, 1);
        st.s0 += __shfl_xor_sync(0xffffffffu, st.s0, 2);
        st.s1 += __shfl_xor_sync(0xffffffffu, st.s1, 1);
        st.s1 += __shfl_xor_sync(0xffffffffu, st.s1, 2);
        float i0 = 1.f / st.s0, i1 = 1.f / st.s1;

        #pragma unroll
        for (int nh = 0; nh < 4; nh++) {
            int col = h * HD + nh * 8 + 2 * qd;
            if (r0 < NTOK)
                *(float2*)&g_ao[((size_t)b * NTOK + r0) * DIMC + col] =
                    make_float2(st.occ[nh][0] * i0, st.occ[nh][1] * i0);
            if (r1 < NTOK)
                *(float2*)&g_ao[((size_t)b * NTOK + r1) * DIMC + col] =
                    make_float2(st.occ[nh][2] * i1, st.occ[nh][3] * i1);
        }
    }
}

// ---------------------------------------------------------------------------
// Kernel 4: tf32-MMA projection GEMM [MROWS x 192] @ [192 x 192] (+bias)
// ---------------------------------------------------------------------------
__global__ __launch_bounds__(256) void proj_gemm_tc(const float* __restrict__ W,
                                                    const float* __restrict__ bias,
                                                    float* __restrict__ out)
{
    __shared__ float As[128 * GSTR];
    __shared__ float Bs[64 * GSTR];
    int tid = threadIdx.x, lane = tid & 31, warp = tid >> 5;
    int gid = lane >> 2, qd = lane & 3;
    int m0 = blockIdx.y * 128, n0 = blockIdx.x * 64;
    int mrow = (warp & 3) * 32, ncol = (warp >> 2) * 32;
    int arow = tid >> 1, ac0 = (tid & 1) * 16;
    int brow = tid >> 2, bc0 = (tid & 3) * 8;

    float c[2][4][4];
    #pragma unroll
    for (int mt = 0; mt < 2; mt++)
        #pragma unroll
        for (int nt = 0; nt < 4; nt++)
            #pragma unroll
            for (int i = 0; i < 4; i++) c[mt][nt][i] = 0.f;

    for (int k0 = 0; k0 < DIMC; k0 += 32) {
        #pragma unroll
        for (int i = 0; i < 4; i++) {
            float4 v = *(const float4*)&g_ao[(size_t)(m0 + arow) * DIMC + k0 + ac0 + i * 4];
            v.x = to_tf32(v.x); v.y = to_tf32(v.y); v.z = to_tf32(v.z); v.w = to_tf32(v.w);
            *(float4*)&As[arow * GSTR + ac0 + i * 4] = v;
        }
        #pragma unroll
        for (int i = 0; i < 2; i++) {
            float4 v = *(const float4*)&W[(size_t)(n0 + brow) * DIMC + k0 + bc0 + i * 4];
            v.x = to_tf32(v.x); v.y = to_tf32(v.y); v.z = to_tf32(v.z); v.w = to_tf32(v.w);
            *(float4*)&Bs[brow * GSTR + bc0 + i * 4] = v;
        }
        __syncthreads();
        #pragma unroll
        for (int k8 = 0; k8 < 4; k8++) {
            int kk = k8 * 8;
            float a[2][4], b[4][2];
            #pragma unroll
            for (int mt = 0; mt < 2; mt++) {
                int r = mrow + mt * 16 + gid;
                a[mt][0] = As[r * GSTR + kk + qd];
                a[mt][1] = As[(r + 8) * GSTR + kk + qd];
                a[mt][2] = As[r * GSTR + kk + qd + 4];
                a[mt][3] = As[(r + 8) * GSTR + kk + qd + 4];
            }
            #pragma unroll
            for (int nt = 0; nt < 4; nt++) {
                int rn = ncol + nt * 8 + gid;
                b[nt][0] = Bs[rn * GSTR + kk + qd];
                b[nt][1] = Bs[rn * GSTR + kk + qd + 4];
            }
            #pragma unroll
            for (int mt = 0; mt < 2; mt++)
                #pragma unroll
                for (int nt = 0; nt < 4; nt++)
                    mma_tf32(c[mt][nt], a[mt], b[nt][0], b[nt][1]);
        }
        __syncthreads();
    }

    #pragma unroll
    for (int mt = 0; mt < 2; mt++) {
        int gmA = m0 + mrow + mt * 16 + gid, gmB = gmA + 8;
        #pragma unroll
        for (int nt = 0; nt < 4; nt++) {
            int gn = n0 + ncol + nt * 8 + 2 * qd;
            float b0 = bias[gn], b1 = bias[gn + 1];
            *(float2*)&out[(size_t)gmA * DIMC + gn] =
                make_float2(c[mt][nt][0] + b0, c[mt][nt][1] + b1);
            *(float2*)&out[(size_t)gmB * DIMC + gn] =
                make_float2(c[mt][nt][2] + b0, c[mt][nt][3] + b1);
        }
    }
}

// ---------------------------------------------------------------------------
extern "C" void kernel_launch(void* const* d_in, const int* in_sizes, int n_in,
                              void* d_out, int out_size)
{
    const float* x      = (const float*)d_in[0];
    const float* mask   = (const float*)d_in[1];
    const float* qkv_w  = (const float*)d_in[2];
    const float* qkv_b  = (const float*)d_in[3];
    const float* rpb    = (const float*)d_in[4];
    const float* proj_w = (const float*)d_in[5];
    const float* proj_b = (const float*)d_in[6];
    float* out = (float*)d_out;

    (void)in_sizes; (void)n_in; (void)out_size;

    int smem = (344 * KSTR + 344 * VSTR + 352 * QSTR) * (int)sizeof(float);
    cudaFuncSetAttribute(attn_tc, cudaFuncAttributeMaxDynamicSharedMemorySize, smem);

    bm_kernel<<<dim3(NTOK, NWIN * NHEADS), 128>>>(rpb, mask);
    qkv_gemm_tc<<<dim3(QKVN / 64, MROWS / 128), 256>>>(x, qkv_w, qkv_b);
    attn_tc<<<dim3(NHEADS, NB), 512, smem>>>();
    proj_gemm_tc<<<dim3(DIMC / 64, MROWS / 128), 256>>>(proj_w, proj_b, out);
}

// round 9
// speedup vs baseline: 3.3554x; 1.1295x over previous
#include <cuda_runtime.h>
#include <cuda_fp16.h>
#include <math.h>

#define NHEADS 6
#define NTOK   343
#define DIMC   192
#define HD     32
#define NB     256
#define NWIN   64
#define MROWS  (NB*NTOK)      // 87808
#define QKVN   576
#define SCALEF 0.17677669529663687f

#define KSTRH  40    // K smem stride (halves)  : 20 words %32 -> conflict-free
#define QSTRH  40
#define VTSTRH 360   // V^T smem stride (halves): 180 words %32==20 -> conflict-free
#define BMSTR  352   // bm row stride (floats)
#define GSTR   36    // gemm smem stride

// ---- scratch (device globals; no runtime allocation) ----
__device__ __half g_q[(size_t)NB*NHEADS*NTOK*HD];
__device__ __half g_k[(size_t)NB*NHEADS*NTOK*HD];
__device__ __half g_v[(size_t)NB*NHEADS*NTOK*HD];
__device__ float  g_bm[(size_t)NWIN*NHEADS*NTOK*BMSTR];
__device__ float  g_ao[(size_t)NB*NTOK*DIMC];

__device__ __forceinline__ float to_tf32(float x) {
    float r;
    asm("cvt.rna.tf32.f32 %0, %1;" : "=f"(r) : "f"(x));
    return r;
}

__device__ __forceinline__ void mma_tf32(float* c, const float* a, float b0f, float b1f) {
    unsigned A0 = __float_as_uint(a[0]), A1 = __float_as_uint(a[1]);
    unsigned A2 = __float_as_uint(a[2]), A3 = __float_as_uint(a[3]);
    unsigned B0 = __float_as_uint(b0f),  B1 = __float_as_uint(b1f);
    asm volatile(
        "mma.sync.aligned.m16n8k8.row.col.f32.tf32.tf32.f32 "
        "{%0,%1,%2,%3}, {%4,%5,%6,%7}, {%8,%9}, {%0,%1,%2,%3};"
        : "+f"(c[0]), "+f"(c[1]), "+f"(c[2]), "+f"(c[3])
        : "r"(A0), "r"(A1), "r"(A2), "r"(A3), "r"(B0), "r"(B1));
}

__device__ __forceinline__ void mma_f16(float* c, const unsigned* a, unsigned b0, unsigned b1) {
    asm volatile(
        "mma.sync.aligned.m16n8k16.row.col.f32.f16.f16.f32 "
        "{%0,%1,%2,%3}, {%4,%5,%6,%7}, {%8,%9}, {%0,%1,%2,%3};"
        : "+f"(c[0]), "+f"(c[1]), "+f"(c[2]), "+f"(c[3])
        : "r"(a[0]), "r"(a[1]), "r"(a[2]), "r"(a[3]), "r"(b0), "r"(b1));
}

__device__ __forceinline__ unsigned pack_h2(float a, float b) {
    __half2 h = __floats2half2_rn(a, b);
    return *(unsigned*)&h;
}

// ---------------------------------------------------------------------------
// Kernel 1: fuse rpb gather + mask into g_bm[(w*6+h)][i][j], rows padded 352
// ---------------------------------------------------------------------------
__global__ void bm_kernel(const float* __restrict__ rpb, const float* __restrict__ mask)
{
    int i  = blockIdx.x;          // 0..342
    int wh = blockIdx.y;          // w*6+h
    int w  = wh / NHEADS, h = wh - w * NHEADS;
    int di = i / 49, hi = (i / 7) % 7, wi = i % 7;
    float* dst = g_bm + ((size_t)wh * NTOK + i) * BMSTR;
    const float* mrow = mask + ((size_t)w * NTOK + i) * NTOK;
    for (int j = threadIdx.x; j < BMSTR; j += 128) {
        float val = 0.f;
        if (j < NTOK) {
            int dj = j / 49, hj = (j / 7) % 7, wj = j % 7;
            int idx = (di - dj + 6) * 169 + (hi - hj + 6) * 13 + (wi - wj + 6);
            val = rpb[idx * NHEADS + h] + mrow[j];
        }
        dst[j] = val;
    }
}

// ---------------------------------------------------------------------------
// Kernel 2: tf32-MMA QKV GEMM; epilogue writes q/k/v as fp16 (q pre-scaled)
// ---------------------------------------------------------------------------
__global__ __launch_bounds__(256) void qkv_gemm_tc(const float* __restrict__ X,
                                                   const float* __restrict__ W,
                                                   const float* __restrict__ bias)
{
    __shared__ float As[128 * GSTR];
    __shared__ float Bs[64 * GSTR];
    int tid = threadIdx.x, lane = tid & 31, warp = tid >> 5;
    int gid = lane >> 2, qd = lane & 3;
    int m0 = blockIdx.y * 128, n0 = blockIdx.x * 64;
    int mrow = (warp & 3) * 32, ncol = (warp >> 2) * 32;
    int arow = tid >> 1, ac0 = (tid & 1) * 16;
    int brow = tid >> 2, bc0 = (tid & 3) * 8;

    float c[2][4][4];
    #pragma unroll
    for (int mt = 0; mt < 2; mt++)
        #pragma unroll
        for (int nt = 0; nt < 4; nt++)
            #pragma unroll
            for (int i = 0; i < 4; i++) c[mt][nt][i] = 0.f;

    for (int k0 = 0; k0 < DIMC; k0 += 32) {
        #pragma unroll
        for (int i = 0; i < 4; i++) {
            float4 v = *(const float4*)&X[(size_t)(m0 + arow) * DIMC + k0 + ac0 + i * 4];
            v.x = to_tf32(v.x); v.y = to_tf32(v.y); v.z = to_tf32(v.z); v.w = to_tf32(v.w);
            *(float4*)&As[arow * GSTR + ac0 + i * 4] = v;
        }
        #pragma unroll
        for (int i = 0; i < 2; i++) {
            float4 v = *(const float4*)&W[(size_t)(n0 + brow) * DIMC + k0 + bc0 + i * 4];
            v.x = to_tf32(v.x); v.y = to_tf32(v.y); v.z = to_tf32(v.z); v.w = to_tf32(v.w);
            *(float4*)&Bs[brow * GSTR + bc0 + i * 4] = v;
        }
        __syncthreads();
        #pragma unroll
        for (int k8 = 0; k8 < 4; k8++) {
            int kk = k8 * 8;
            float a[2][4], b[4][2];
            #pragma unroll
            for (int mt = 0; mt < 2; mt++) {
                int r = mrow + mt * 16 + gid;
                a[mt][0] = As[r * GSTR + kk + qd];
                a[mt][1] = As[(r + 8) * GSTR + kk + qd];
                a[mt][2] = As[r * GSTR + kk + qd + 4];
                a[mt][3] = As[(r + 8) * GSTR + kk + qd + 4];
            }
            #pragma unroll
            for (int nt = 0; nt < 4; nt++) {
                int rn = ncol + nt * 8 + gid;
                b[nt][0] = Bs[rn * GSTR + kk + qd];
                b[nt][1] = Bs[rn * GSTR + kk + qd + 4];
            }
            #pragma unroll
            for (int mt = 0; mt < 2; mt++)
                #pragma unroll
                for (int nt = 0; nt < 4; nt++)
                    mma_tf32(c[mt][nt], a[mt], b[nt][0], b[nt][1]);
        }
        __syncthreads();
    }

    #pragma unroll
    for (int mt = 0; mt < 2; mt++) {
        int gmA = m0 + mrow + mt * 16 + gid, gmB = gmA + 8;
        int bA = gmA / NTOK, tA = gmA - bA * NTOK;
        int bB = gmB / NTOK, tB = gmB - bB * NTOK;
        #pragma unroll
        for (int nt = 0; nt < 4; nt++) {
            int gn = n0 + ncol + nt * 8 + 2 * qd;
            int sec = gn / DIMC, rem = gn - sec * DIMC;
            int hh = rem >> 5, dd = rem & 31;
            float b0 = bias[gn], b1 = bias[gn + 1];
            float vA0 = c[mt][nt][0] + b0, vA1 = c[mt][nt][1] + b1;
            float vB0 = c[mt][nt][2] + b0, vB1 = c[mt][nt][3] + b1;
            size_t offA = (((size_t)bA * NHEADS + hh) * NTOK + tA) * HD + dd;
            size_t offB = (((size_t)bB * NHEADS + hh) * NTOK + tB) * HD + dd;
            if (sec == 0) {
                *(__half2*)&g_q[offA] = __floats2half2_rn(vA0 * SCALEF, vA1 * SCALEF);
                *(__half2*)&g_q[offB] = __floats2half2_rn(vB0 * SCALEF, vB1 * SCALEF);
            } else if (sec == 1) {
                *(__half2*)&g_k[offA] = __floats2half2_rn(vA0, vA1);
                *(__half2*)&g_k[offB] = __floats2half2_rn(vB0, vB1);
            } else {
                *(__half2*)&g_v[offA] = __floats2half2_rn(vA0, vA1);
                *(__half2*)&g_v[offB] = __floats2half2_rn(vB0, vB1);
            }
        }
    }
}

// ---------------------------------------------------------------------------
// Kernel 3: fp16 register-resident flash attention, 2 blocks/SM.
// ---------------------------------------------------------------------------
template<bool MASK>
__device__ __forceinline__ void attn_pair(int pr, int gid, int qd,
                                          const __half* __restrict__ Ks,
                                          const __half* __restrict__ Vt,
                                          const float* __restrict__ bmA,
                                          const float* __restrict__ bmB,
                                          const unsigned a[2][4], float occ[4][4],
                                          float& m0, float& m1, float& s0, float& s1)
{
    int kb0 = pr * 16;
    float c[2][4];
    #pragma unroll
    for (int sub = 0; sub < 2; sub++) {
        c[sub][0] = c[sub][1] = c[sub][2] = c[sub][3] = 0.f;
        int kb = kb0 + sub * 8;
        const __half* krow = &Ks[(kb + gid) * KSTRH + 2 * qd];
        #pragma unroll
        for (int ks = 0; ks < 2; ks++) {
            unsigned b0 = *(const unsigned*)&krow[ks * 16];
            unsigned b1 = *(const unsigned*)&krow[ks * 16 + 8];
            mma_f16(c[sub], a[ks], b0, b1);
        }
        float2 mA = *(const float2*)&bmA[kb + 2 * qd];
        float2 mB = *(const float2*)&bmB[kb + 2 * qd];
        c[sub][0] += mA.x; c[sub][1] += mA.y;
        c[sub][2] += mB.x; c[sub][3] += mB.y;
        if (MASK) {
            int k0 = kb + 2 * qd;
            if (k0 >= NTOK)     { c[sub][0] = -1e30f; c[sub][2] = -1e30f; }
            if (k0 + 1 >= NTOK) { c[sub][1] = -1e30f; c[sub][3] = -1e30f; }
        }
    }
    float cm0 = fmaxf(fmaxf(c[0][0], c[0][1]), fmaxf(c[1][0], c[1][1]));
    float cm1 = fmaxf(fmaxf(c[0][2], c[0][3]), fmaxf(c[1][2], c[1][3]));
    cm0 = fmaxf(cm0, __shfl_xor_sync(0xffffffffu, cm0, 1));
    cm0 = fmaxf(cm0, __shfl_xor_sync(0xffffffffu, cm0, 2));
    cm1 = fmaxf(cm1, __shfl_xor_sync(0xffffffffu, cm1, 1));
    cm1 = fmaxf(cm1, __shfl_xor_sync(0xffffffffu, cm1, 2));
    float mn0 = fmaxf(m0, cm0), mn1 = fmaxf(m1, cm1);
    float sc0 = __expf(m0 - mn0), sc1 = __expf(m1 - mn1);
    m0 = mn0; m1 = mn1;
    s0 *= sc0; s1 *= sc1;
    #pragma unroll
    for (int nh = 0; nh < 4; nh++) {
        occ[nh][0] *= sc0; occ[nh][1] *= sc0;
        occ[nh][2] *= sc1; occ[nh][3] *= sc1;
    }
    float e00 = __expf(c[0][0] - m0), e01 = __expf(c[0][1] - m0);
    float e02 = __expf(c[0][2] - m1), e03 = __expf(c[0][3] - m1);
    float e10 = __expf(c[1][0] - m0), e11 = __expf(c[1][1] - m0);
    float e12 = __expf(c[1][2] - m1), e13 = __expf(c[1][3] - m1);
    s0 += e00 + e01 + e10 + e11;
    s1 += e02 + e03 + e12 + e13;
    unsigned pa[4];
    pa[0] = pack_h2(e00, e01);
    pa[1] = pack_h2(e02, e03);
    pa[2] = pack_h2(e10, e11);
    pa[3] = pack_h2(e12, e13);
    #pragma unroll
    for (int nh = 0; nh < 4; nh++) {
        const __half* vrow = &Vt[(nh * 8 + gid) * VTSTRH + kb0 + 2 * qd];
        unsigned b0 = *(const unsigned*)&vrow[0];
        unsigned b1 = *(const unsigned*)&vrow[8];
        mma_f16(occ[nh], pa, b0, b1);
    }
}

__global__ __launch_bounds__(512, 2) void attn_tc()
{
    extern __shared__ __half smh[];
    __half* Ks = smh;                      // 352*40 [key][hd]
    __half* Vt = Ks + 352 * KSTRH;         // 32*360 [hd][key]
    __half* Qs = Vt + 32 * VTSTRH;         // 352*40 [q][hd]

    int tid  = threadIdx.x;
    int h    = blockIdx.x;
    int b    = blockIdx.y;
    int w    = b & (NWIN - 1);
    int lane = tid & 31, warp = tid >> 5;
    int gid  = lane >> 2, qd = lane & 3;

    size_t base = (((size_t)b * NHEADS) + h) * NTOK * HD;
    const __half* qg = g_q + base;
    const __half* kg = g_k + base;
    const __half* vg = g_v + base;
    const float*  bm = g_bm + (size_t)(w * NHEADS + h) * NTOK * BMSTR;

    __half2 zero2 = __floats2half2_rn(0.f, 0.f);
    for (int i = tid; i < 352 * 16; i += 512) {
        int j = i >> 4, d2 = (i & 15) * 2;
        __half2 kv = zero2, vv = zero2;
        if (j < NTOK) {
            kv = *(const __half2*)&kg[j * HD + d2];
            vv = *(const __half2*)&vg[j * HD + d2];
        }
        *(__half2*)&Ks[j * KSTRH + d2] = kv;
        Vt[d2 * VTSTRH + j]       = __low2half(vv);
        Vt[(d2 + 1) * VTSTRH + j] = __high2half(vv);
        int t = j > NTOK - 1 ? NTOK - 1 : j;
        *(__half2*)&Qs[j * QSTRH + d2] = *(const __half2*)&qg[t * HD + d2];
    }
    __syncthreads();

    for (int wt = warp; wt < 22; wt += 16) {
        int r0 = wt * 16 + gid, r1 = r0 + 8;
        int tA = r0 > NTOK - 1 ? NTOK - 1 : r0;
        int tB = r1 > NTOK - 1 ? NTOK - 1 : r1;

        unsigned a[2][4];
        #pragma unroll
        for (int ks = 0; ks < 2; ks++) {
            a[ks][0] = *(const unsigned*)&Qs[r0 * QSTRH + ks * 16 + 2 * qd];
            a[ks][1] = *(const unsigned*)&Qs[r1 * QSTRH + ks * 16 + 2 * qd];
            a[ks][2] = *(const unsigned*)&Qs[r0 * QSTRH + ks * 16 + 8 + 2 * qd];
            a[ks][3] = *(const unsigned*)&Qs[r1 * QSTRH + ks * 16 + 8 + 2 * qd];
        }
        float occ[4][4];
        #pragma unroll
        for (int nh = 0; nh < 4; nh++)
            #pragma unroll
            for (int i = 0; i < 4; i++) occ[nh][i] = 0.f;
        float m0 = -1e30f, m1 = -1e30f, s0 = 0.f, s1 = 0.f;

        const float* bmA = bm + (size_t)tA * BMSTR;
        const float* bmB = bm + (size_t)tB * BMSTR;

        #pragma unroll 1
        for (int pr = 0; pr < 21; pr++)
            attn_pair<false>(pr, gid, qd, Ks, Vt, bmA, bmB, a, occ, m0, m1, s0, s1);
        attn_pair<true>(21, gid, qd, Ks, Vt, bmA, bmB, a, occ, m0, m1, s0, s1);

        s0 += __shfl_xor_sync(0xffffffffu, s0, 1);
        s0 += __shfl_xor_sync(0xffffffffu, s0, 2);
        s1 += __shfl_xor_sync(0xffffffffu, s1, 1);
        s1 += __shfl_xor_sync(0xffffffffu, s1, 2);
        float i0 = 1.f / s0, i1 = 1.f / s1;

        #pragma unroll
        for (int nh = 0; nh < 4; nh++) {
            int col = h * HD + nh * 8 + 2 * qd;
            if (r0 < NTOK)
                *(float2*)&g_ao[((size_t)b * NTOK + r0) * DIMC + col] =
                    make_float2(occ[nh][0] * i0, occ[nh][1] * i0);
            if (r1 < NTOK)
                *(float2*)&g_ao[((size_t)b * NTOK + r1) * DIMC + col] =
                    make_float2(occ[nh][2] * i1, occ[nh][3] * i1);
        }
    }
}

// ---------------------------------------------------------------------------
// Kernel 4: tf32-MMA projection GEMM [MROWS x 192] @ [192 x 192] (+bias)
// ---------------------------------------------------------------------------
__global__ __launch_bounds__(256) void proj_gemm_tc(const float* __restrict__ W,
                                                    const float* __restrict__ bias,
                                                    float* __restrict__ out)
{
    __shared__ float As[128 * GSTR];
    __shared__ float Bs[64 * GSTR];
    int tid = threadIdx.x, lane = tid & 31, warp = tid >> 5;
    int gid = lane >> 2, qd = lane & 3;
    int m0 = blockIdx.y * 128, n0 = blockIdx.x * 64;
    int mrow = (warp & 3) * 32, ncol = (warp >> 2) * 32;
    int arow = tid >> 1, ac0 = (tid & 1) * 16;
    int brow = tid >> 2, bc0 = (tid & 3) * 8;

    float c[2][4][4];
    #pragma unroll
    for (int mt = 0; mt < 2; mt++)
        #pragma unroll
        for (int nt = 0; nt < 4; nt++)
            #pragma unroll
            for (int i = 0; i < 4; i++) c[mt][nt][i] = 0.f;

    for (int k0 = 0; k0 < DIMC; k0 += 32) {
        #pragma unroll
        for (int i = 0; i < 4; i++) {
            float4 v = *(const float4*)&g_ao[(size_t)(m0 + arow) * DIMC + k0 + ac0 + i * 4];
            v.x = to_tf32(v.x); v.y = to_tf32(v.y); v.z = to_tf32(v.z); v.w = to_tf32(v.w);
            *(float4*)&As[arow * GSTR + ac0 + i * 4] = v;
        }
        #pragma unroll
        for (int i = 0; i < 2; i++) {
            float4 v = *(const float4*)&W[(size_t)(n0 + brow) * DIMC + k0 + bc0 + i * 4];
            v.x = to_tf32(v.x); v.y = to_tf32(v.y); v.z = to_tf32(v.z); v.w = to_tf32(v.w);
            *(float4*)&Bs[brow * GSTR + bc0 + i * 4] = v;
        }
        __syncthreads();
        #pragma unroll
        for (int k8 = 0; k8 < 4; k8++) {
            int kk = k8 * 8;
            float a[2][4], b[4][2];
            #pragma unroll
            for (int mt = 0; mt < 2; mt++) {
                int r = mrow + mt * 16 + gid;
                a[mt][0] = As[r * GSTR + kk + qd];
                a[mt][1] = As[(r + 8) * GSTR + kk + qd];
                a[mt][2] = As[r * GSTR + kk + qd + 4];
                a[mt][3] = As[(r + 8) * GSTR + kk + qd + 4];
            }
            #pragma unroll
            for (int nt = 0; nt < 4; nt++) {
                int rn = ncol + nt * 8 + gid;
                b[nt][0] = Bs[rn * GSTR + kk + qd];
                b[nt][1] = Bs[rn * GSTR + kk + qd + 4];
            }
            #pragma unroll
            for (int mt = 0; mt < 2; mt++)
                #pragma unroll
                for (int nt = 0; nt < 4; nt++)
                    mma_tf32(c[mt][nt], a[mt], b[nt][0], b[nt][1]);
        }
        __syncthreads();
    }

    #pragma unroll
    for (int mt = 0; mt < 2; mt++) {
        int gmA = m0 + mrow + mt * 16 + gid, gmB = gmA + 8;
        #pragma unroll
        for (int nt = 0; nt < 4; nt++) {
            int gn = n0 + ncol + nt * 8 + 2 * qd;
            float b0 = bias[gn], b1 = bias[gn + 1];
            *(float2*)&out[(size_t)gmA * DIMC + gn] =
                make_float2(c[mt][nt][0] + b0, c[mt][nt][1] + b1);
            *(float2*)&out[(size_t)gmB * DIMC + gn] =
                make_float2(c[mt][nt][2] + b0, c[mt][nt][3] + b1);
        }
    }
}

// ---------------------------------------------------------------------------
extern "C" void kernel_launch(void* const* d_in, const int* in_sizes, int n_in,
                              void* d_out, int out_size)
{
    const float* x      = (const float*)d_in[0];
    const float* mask   = (const float*)d_in[1];
    const float* qkv_w  = (const float*)d_in[2];
    const float* qkv_b  = (const float*)d_in[3];
    const float* rpb    = (const float*)d_in[4];
    const float* proj_w = (const float*)d_in[5];
    const float* proj_b = (const float*)d_in[6];
    float* out = (float*)d_out;

    (void)in_sizes; (void)n_in; (void)out_size;

    int smem = (352 * KSTRH + 32 * VTSTRH + 352 * QSTRH) * (int)sizeof(__half);
    cudaFuncSetAttribute(attn_tc, cudaFuncAttributeMaxDynamicSharedMemorySize, smem);

    bm_kernel<<<dim3(NTOK, NWIN * NHEADS), 128>>>(rpb, mask);
    qkv_gemm_tc<<<dim3(QKVN / 64, MROWS / 128), 256>>>(x, qkv_w, qkv_b);
    attn_tc<<<dim3(NHEADS, NB), 512, smem>>>();
    proj_gemm_tc<<<dim3(DIMC / 64, MROWS / 128), 256>>>(proj_w, proj_b, out);
}

// round 10
// speedup vs baseline: 3.7495x; 1.1175x over previous
#include <cuda_runtime.h>
#include <cuda_fp16.h>
#include <math.h>

#define NHEADS 6
#define NTOK   343
#define DIMC   192
#define HD     32
#define NB     256
#define NWIN   64
#define MROWS  (NB*NTOK)      // 87808
#define QKVN   576
#define SCALEF 0.17677669529663687f

#define KSTRH  40    // attn K/Q smem stride (halves)
#define QSTRH  40
#define VTSTRH 360   // attn V^T smem stride (halves)
#define BMSTR  352   // bm row stride (floats)
#define XSTR   200   // gemm smem row stride (halves): (4r+c/2)%32 distinct -> conflict-free

// ---- scratch (device globals; no runtime allocation) ----
__device__ __half g_q[(size_t)NB*NHEADS*NTOK*HD];
__device__ __half g_k[(size_t)NB*NHEADS*NTOK*HD];
__device__ __half g_v[(size_t)NB*NHEADS*NTOK*HD];
__device__ float  g_bm[(size_t)NWIN*NHEADS*NTOK*BMSTR];
__device__ __half g_ao[(size_t)NB*NTOK*DIMC];

__device__ __forceinline__ void mma_f16(float* c, const unsigned* a, unsigned b0, unsigned b1) {
    asm volatile(
        "mma.sync.aligned.m16n8k16.row.col.f32.f16.f16.f32 "
        "{%0,%1,%2,%3}, {%4,%5,%6,%7}, {%8,%9}, {%0,%1,%2,%3};"
        : "+f"(c[0]), "+f"(c[1]), "+f"(c[2]), "+f"(c[3])
        : "r"(a[0]), "r"(a[1]), "r"(a[2]), "r"(a[3]), "r"(b0), "r"(b1));
}

__device__ __forceinline__ unsigned pack_h2(float a, float b) {
    __half2 h = __floats2half2_rn(a, b);
    return *(unsigned*)&h;
}

// ---------------------------------------------------------------------------
// Kernel 1: fuse rpb gather + mask into g_bm[(w*6+h)][i][j], rows padded 352
// ---------------------------------------------------------------------------
__global__ void bm_kernel(const float* __restrict__ rpb, const float* __restrict__ mask)
{
    int i  = blockIdx.x;
    int wh = blockIdx.y;
    int w  = wh / NHEADS, h = wh - w * NHEADS;
    int di = i / 49, hi = (i / 7) % 7, wi = i % 7;
    float* dst = g_bm + ((size_t)wh * NTOK + i) * BMSTR;
    const float* mrow = mask + ((size_t)w * NTOK + i) * NTOK;
    for (int j = threadIdx.x; j < BMSTR; j += 128) {
        float val = 0.f;
        if (j < NTOK) {
            int dj = j / 49, hj = (j / 7) % 7, wj = j % 7;
            int idx = (di - dj + 6) * 169 + (hi - hj + 6) * 13 + (wi - wj + 6);
            val = rpb[idx * NHEADS + h] + mrow[j];
        }
        dst[j] = val;
    }
}

// ---------------------------------------------------------------------------
// Kernel 2: fp16-MMA QKV GEMM [MROWS x 192] @ W^T[192 x 576] (+bias), scatter.
// Full K resident in smem; one __syncthreads; 12 unrolled k16 steps.
// ---------------------------------------------------------------------------
__global__ __launch_bounds__(256) void qkv_gemm_f16(const float* __restrict__ X,
                                                    const float* __restrict__ W,
                                                    const float* __restrict__ bias)
{
    extern __shared__ __half gs[];
    __half* Xs = gs;                 // 128 x XSTR
    __half* Ws = gs + 128 * XSTR;    // 64  x XSTR
    int tid = threadIdx.x, lane = tid & 31, warp = tid >> 5;
    int gid = lane >> 2, qd = lane & 3;
    int m0 = blockIdx.y * 128, n0 = blockIdx.x * 64;
    int mrow = (warp & 3) * 32, ncol = (warp >> 2) * 32;

    for (int idx = tid; idx < 128 * 48; idx += 256) {
        int r = idx / 48, c4 = idx % 48;
        float4 v = *(const float4*)&X[(size_t)(m0 + r) * DIMC + c4 * 4];
        *(__half2*)&Xs[r * XSTR + c4 * 4]     = __floats2half2_rn(v.x, v.y);
        *(__half2*)&Xs[r * XSTR + c4 * 4 + 2] = __floats2half2_rn(v.z, v.w);
    }
    for (int idx = tid; idx < 64 * 48; idx += 256) {
        int r = idx / 48, c4 = idx % 48;
        float4 v = *(const float4*)&W[(size_t)(n0 + r) * DIMC + c4 * 4];
        *(__half2*)&Ws[r * XSTR + c4 * 4]     = __floats2half2_rn(v.x, v.y);
        *(__half2*)&Ws[r * XSTR + c4 * 4 + 2] = __floats2half2_rn(v.z, v.w);
    }
    __syncthreads();

    float c[2][4][4];
    #pragma unroll
    for (int mt = 0; mt < 2; mt++)
        #pragma unroll
        for (int nt = 0; nt < 4; nt++)
            #pragma unroll
            for (int i = 0; i < 4; i++) c[mt][nt][i] = 0.f;

    #pragma unroll
    for (int ks = 0; ks < 12; ks++) {
        int kk = ks * 16;
        unsigned a[2][4], bf[4][2];
        #pragma unroll
        for (int mt = 0; mt < 2; mt++) {
            int r = mrow + mt * 16 + gid;
            a[mt][0] = *(const unsigned*)&Xs[r * XSTR + kk + 2 * qd];
            a[mt][1] = *(const unsigned*)&Xs[(r + 8) * XSTR + kk + 2 * qd];
            a[mt][2] = *(const unsigned*)&Xs[r * XSTR + kk + 8 + 2 * qd];
            a[mt][3] = *(const unsigned*)&Xs[(r + 8) * XSTR + kk + 8 + 2 * qd];
        }
        #pragma unroll
        for (int nt = 0; nt < 4; nt++) {
            int rn = ncol + nt * 8 + gid;
            bf[nt][0] = *(const unsigned*)&Ws[rn * XSTR + kk + 2 * qd];
            bf[nt][1] = *(const unsigned*)&Ws[rn * XSTR + kk + 8 + 2 * qd];
        }
        #pragma unroll
        for (int mt = 0; mt < 2; mt++)
            #pragma unroll
            for (int nt = 0; nt < 4; nt++)
                mma_f16(c[mt][nt], a[mt], bf[nt][0], bf[nt][1]);
    }

    #pragma unroll
    for (int mt = 0; mt < 2; mt++) {
        int gmA = m0 + mrow + mt * 16 + gid, gmB = gmA + 8;
        int bA = gmA / NTOK, tA = gmA - bA * NTOK;
        int bB = gmB / NTOK, tB = gmB - bB * NTOK;
        #pragma unroll
        for (int nt = 0; nt < 4; nt++) {
            int gn = n0 + ncol + nt * 8 + 2 * qd;
            int sec = gn / DIMC, rem = gn - sec * DIMC;
            int hh = rem >> 5, dd = rem & 31;
            float b0 = bias[gn], b1 = bias[gn + 1];
            float vA0 = c[mt][nt][0] + b0, vA1 = c[mt][nt][1] + b1;
            float vB0 = c[mt][nt][2] + b0, vB1 = c[mt][nt][3] + b1;
            size_t offA = (((size_t)bA * NHEADS + hh) * NTOK + tA) * HD + dd;
            size_t offB = (((size_t)bB * NHEADS + hh) * NTOK + tB) * HD + dd;
            if (sec == 0) {
                *(__half2*)&g_q[offA] = __floats2half2_rn(vA0 * SCALEF, vA1 * SCALEF);
                *(__half2*)&g_q[offB] = __floats2half2_rn(vB0 * SCALEF, vB1 * SCALEF);
            } else if (sec == 1) {
                *(__half2*)&g_k[offA] = __floats2half2_rn(vA0, vA1);
                *(__half2*)&g_k[offB] = __floats2half2_rn(vB0, vB1);
            } else {
                *(__half2*)&g_v[offA] = __floats2half2_rn(vA0, vA1);
                *(__half2*)&g_v[offB] = __floats2half2_rn(vB0, vB1);
            }
        }
    }
}

// ---------------------------------------------------------------------------
// Kernel 3: fp16 register-resident flash attention, 2 blocks/SM.
// ---------------------------------------------------------------------------
template<bool MASK>
__device__ __forceinline__ void attn_pair(int pr, int gid, int qd,
                                          const __half* __restrict__ Ks,
                                          const __half* __restrict__ Vt,
                                          const float* __restrict__ bmA,
                                          const float* __restrict__ bmB,
                                          const unsigned a[2][4], float occ[4][4],
                                          float& m0, float& m1, float& s0, float& s1)
{
    int kb0 = pr * 16;
    float c[2][4];
    #pragma unroll
    for (int sub = 0; sub < 2; sub++) {
        c[sub][0] = c[sub][1] = c[sub][2] = c[sub][3] = 0.f;
        int kb = kb0 + sub * 8;
        const __half* krow = &Ks[(kb + gid) * KSTRH + 2 * qd];
        #pragma unroll
        for (int ks = 0; ks < 2; ks++) {
            unsigned b0 = *(const unsigned*)&krow[ks * 16];
            unsigned b1 = *(const unsigned*)&krow[ks * 16 + 8];
            mma_f16(c[sub], a[ks], b0, b1);
        }
        float2 mA = *(const float2*)&bmA[kb + 2 * qd];
        float2 mB = *(const float2*)&bmB[kb + 2 * qd];
        c[sub][0] += mA.x; c[sub][1] += mA.y;
        c[sub][2] += mB.x; c[sub][3] += mB.y;
        if (MASK) {
            int k0 = kb + 2 * qd;
            if (k0 >= NTOK)     { c[sub][0] = -1e30f; c[sub][2] = -1e30f; }
            if (k0 + 1 >= NTOK) { c[sub][1] = -1e30f; c[sub][3] = -1e30f; }
        }
    }
    float cm0 = fmaxf(fmaxf(c[0][0], c[0][1]), fmaxf(c[1][0], c[1][1]));
    float cm1 = fmaxf(fmaxf(c[0][2], c[0][3]), fmaxf(c[1][2], c[1][3]));
    cm0 = fmaxf(cm0, __shfl_xor_sync(0xffffffffu, cm0, 1));
    cm0 = fmaxf(cm0, __shfl_xor_sync(0xffffffffu, cm0, 2));
    cm1 = fmaxf(cm1, __shfl_xor_sync(0xffffffffu, cm1, 1));
    cm1 = fmaxf(cm1, __shfl_xor_sync(0xffffffffu, cm1, 2));
    float mn0 = fmaxf(m0, cm0), mn1 = fmaxf(m1, cm1);
    float sc0 = __expf(m0 - mn0), sc1 = __expf(m1 - mn1);
    m0 = mn0; m1 = mn1;
    s0 *= sc0; s1 *= sc1;
    #pragma unroll
    for (int nh = 0; nh < 4; nh++) {
        occ[nh][0] *= sc0; occ[nh][1] *= sc0;
        occ[nh][2] *= sc1; occ[nh][3] *= sc1;
    }
    float e00 = __expf(c[0][0] - m0), e01 = __expf(c[0][1] - m0);
    float e02 = __expf(c[0][2] - m1), e03 = __expf(c[0][3] - m1);
    float e10 = __expf(c[1][0] - m0), e11 = __expf(c[1][1] - m0);
    float e12 = __expf(c[1][2] - m1), e13 = __expf(c[1][3] - m1);
    s0 += e00 + e01 + e10 + e11;
    s1 += e02 + e03 + e12 + e13;
    unsigned pa[4];
    pa[0] = pack_h2(e00, e01);
    pa[1] = pack_h2(e02, e03);
    pa[2] = pack_h2(e10, e11);
    pa[3] = pack_h2(e12, e13);
    #pragma unroll
    for (int nh = 0; nh < 4; nh++) {
        const __half* vrow = &Vt[(nh * 8 + gid) * VTSTRH + kb0 + 2 * qd];
        unsigned b0 = *(const unsigned*)&vrow[0];
        unsigned b1 = *(const unsigned*)&vrow[8];
        mma_f16(occ[nh], pa, b0, b1);
    }
}

__global__ __launch_bounds__(512, 2) void attn_tc()
{
    extern __shared__ __half smh[];
    __half* Ks = smh;                      // 352*40 [key][hd]
    __half* Vt = Ks + 352 * KSTRH;         // 32*360 [hd][key]
    __half* Qs = Vt + 32 * VTSTRH;         // 352*40 [q][hd]

    int tid  = threadIdx.x;
    int h    = blockIdx.x;
    int b    = blockIdx.y;
    int w    = b & (NWIN - 1);
    int lane = tid & 31, warp = tid >> 5;
    int gid  = lane >> 2, qd = lane & 3;

    size_t base = (((size_t)b * NHEADS) + h) * NTOK * HD;
    const __half* qg = g_q + base;
    const __half* kg = g_k + base;
    const __half* vg = g_v + base;
    const float*  bm = g_bm + (size_t)(w * NHEADS + h) * NTOK * BMSTR;

    __half2 zero2 = __floats2half2_rn(0.f, 0.f);
    for (int i = tid; i < 352 * 16; i += 512) {
        int j = i >> 4, d2 = (i & 15) * 2;
        __half2 kv = zero2, vv = zero2;
        if (j < NTOK) {
            kv = *(const __half2*)&kg[j * HD + d2];
            vv = *(const __half2*)&vg[j * HD + d2];
        }
        *(__half2*)&Ks[j * KSTRH + d2] = kv;
        Vt[d2 * VTSTRH + j]       = __low2half(vv);
        Vt[(d2 + 1) * VTSTRH + j] = __high2half(vv);
        int t = j > NTOK - 1 ? NTOK - 1 : j;
        *(__half2*)&Qs[j * QSTRH + d2] = *(const __half2*)&qg[t * HD + d2];
    }
    __syncthreads();

    for (int wt = warp; wt < 22; wt += 16) {
        int r0 = wt * 16 + gid, r1 = r0 + 8;
        int tA = r0 > NTOK - 1 ? NTOK - 1 : r0;
        int tB = r1 > NTOK - 1 ? NTOK - 1 : r1;

        unsigned a[2][4];
        #pragma unroll
        for (int ks = 0; ks < 2; ks++) {
            a[ks][0] = *(const unsigned*)&Qs[r0 * QSTRH + ks * 16 + 2 * qd];
            a[ks][1] = *(const unsigned*)&Qs[r1 * QSTRH + ks * 16 + 2 * qd];
            a[ks][2] = *(const unsigned*)&Qs[r0 * QSTRH + ks * 16 + 8 + 2 * qd];
            a[ks][3] = *(const unsigned*)&Qs[r1 * QSTRH + ks * 16 + 8 + 2 * qd];
        }
        float occ[4][4];
        #pragma unroll
        for (int nh = 0; nh < 4; nh++)
            #pragma unroll
            for (int i = 0; i < 4; i++) occ[nh][i] = 0.f;
        float m0 = -1e30f, m1 = -1e30f, s0 = 0.f, s1 = 0.f;

        const float* bmA = bm + (size_t)tA * BMSTR;
        const float* bmB = bm + (size_t)tB * BMSTR;

        #pragma unroll 1
        for (int pr = 0; pr < 21; pr++)
            attn_pair<false>(pr, gid, qd, Ks, Vt, bmA, bmB, a, occ, m0, m1, s0, s1);
        attn_pair<true>(21, gid, qd, Ks, Vt, bmA, bmB, a, occ, m0, m1, s0, s1);

        s0 += __shfl_xor_sync(0xffffffffu, s0, 1);
        s0 += __shfl_xor_sync(0xffffffffu, s0, 2);
        s1 += __shfl_xor_sync(0xffffffffu, s1, 1);
        s1 += __shfl_xor_sync(0xffffffffu, s1, 2);
        float i0 = 1.f / s0, i1 = 1.f / s1;

        #pragma unroll
        for (int nh = 0; nh < 4; nh++) {
            int col = h * HD + nh * 8 + 2 * qd;
            if (r0 < NTOK)
                *(__half2*)&g_ao[((size_t)b * NTOK + r0) * DIMC + col] =
                    __floats2half2_rn(occ[nh][0] * i0, occ[nh][1] * i0);
            if (r1 < NTOK)
                *(__half2*)&g_ao[((size_t)b * NTOK + r1) * DIMC + col] =
                    __floats2half2_rn(occ[nh][2] * i1, occ[nh][3] * i1);
        }
    }
}

// ---------------------------------------------------------------------------
// Kernel 4: fp16-MMA projection GEMM [MROWS x 192] @ [192 x 192] (+bias).
// A comes from g_ao already in fp16 (zero-conversion copy).
// ---------------------------------------------------------------------------
__global__ __launch_bounds__(256) void proj_gemm_f16(const float* __restrict__ W,
                                                     const float* __restrict__ bias,
                                                     float* __restrict__ out)
{
    extern __shared__ __half gs[];
    __half* As = gs;                 // 128 x XSTR
    __half* Ws = gs + 128 * XSTR;    // 64  x XSTR
    int tid = threadIdx.x, lane = tid & 31, warp = tid >> 5;
    int gid = lane >> 2, qd = lane & 3;
    int m0 = blockIdx.y * 128, n0 = blockIdx.x * 64;
    int mrow = (warp & 3) * 32, ncol = (warp >> 2) * 32;

    for (int idx = tid; idx < 128 * 48; idx += 256) {
        int r = idx / 48, c4 = idx % 48;
        uint2 v = *(const uint2*)&g_ao[(size_t)(m0 + r) * DIMC + c4 * 4];
        *(uint2*)&As[r * XSTR + c4 * 4] = v;
    }
    for (int idx = tid; idx < 64 * 48; idx += 256) {
        int r = idx / 48, c4 = idx % 48;
        float4 v = *(const float4*)&W[(size_t)(n0 + r) * DIMC + c4 * 4];
        *(__half2*)&Ws[r * XSTR + c4 * 4]     = __floats2half2_rn(v.x, v.y);
        *(__half2*)&Ws[r * XSTR + c4 * 4 + 2] = __floats2half2_rn(v.z, v.w);
    }
    __syncthreads();

    float c[2][4][4];
    #pragma unroll
    for (int mt = 0; mt < 2; mt++)
        #pragma unroll
        for (int nt = 0; nt < 4; nt++)
            #pragma unroll
            for (int i = 0; i < 4; i++) c[mt][nt][i] = 0.f;

    #pragma unroll
    for (int ks = 0; ks < 12; ks++) {
        int kk = ks * 16;
        unsigned a[2][4], bf[4][2];
        #pragma unroll
        for (int mt = 0; mt < 2; mt++) {
            int r = mrow + mt * 16 + gid;
            a[mt][0] = *(const unsigned*)&As[r * XSTR + kk + 2 * qd];
            a[mt][1] = *(const unsigned*)&As[(r + 8) * XSTR + kk + 2 * qd];
            a[mt][2] = *(const unsigned*)&As[r * XSTR + kk + 8 + 2 * qd];
            a[mt][3] = *(const unsigned*)&As[(r + 8) * XSTR + kk + 8 + 2 * qd];
        }
        #pragma unroll
        for (int nt = 0; nt < 4; nt++) {
            int rn = ncol + nt * 8 + gid;
            bf[nt][0] = *(const unsigned*)&Ws[rn * XSTR + kk + 2 * qd];
            bf[nt][1] = *(const unsigned*)&Ws[rn * XSTR + kk + 8 + 2 * qd];
        }
        #pragma unroll
        for (int mt = 0; mt < 2; mt++)
            #pragma unroll
            for (int nt = 0; nt < 4; nt++)
                mma_f16(c[mt][nt], a[mt], bf[nt][0], bf[nt][1]);
    }

    #pragma unroll
    for (int mt = 0; mt < 2; mt++) {
        int gmA = m0 + mrow + mt * 16 + gid, gmB = gmA + 8;
        #pragma unroll
        for (int nt = 0; nt < 4; nt++) {
            int gn = n0 + ncol + nt * 8 + 2 * qd;
            float b0 = bias[gn], b1 = bias[gn + 1];
            *(float2*)&out[(size_t)gmA * DIMC + gn] =
                make_float2(c[mt][nt][0] + b0, c[mt][nt][1] + b1);
            *(float2*)&out[(size_t)gmB * DIMC + gn] =
                make_float2(c[mt][nt][2] + b0, c[mt][nt][3] + b1);
        }
    }
}

// ---------------------------------------------------------------------------
extern "C" void kernel_launch(void* const* d_in, const int* in_sizes, int n_in,
                              void* d_out, int out_size)
{
    const float* x      = (const float*)d_in[0];
    const float* mask   = (const float*)d_in[1];
    const float* qkv_w  = (const float*)d_in[2];
    const float* qkv_b  = (const float*)d_in[3];
    const float* rpb    = (const float*)d_in[4];
    const float* proj_w = (const float*)d_in[5];
    const float* proj_b = (const float*)d_in[6];
    float* out = (float*)d_out;

    (void)in_sizes; (void)n_in; (void)out_size;

    int smem_attn = (352 * KSTRH + 32 * VTSTRH + 352 * QSTRH) * (int)sizeof(__half);
    int smem_gemm = 192 * XSTR * (int)sizeof(__half);
    cudaFuncSetAttribute(attn_tc, cudaFuncAttributeMaxDynamicSharedMemorySize, smem_attn);
    cudaFuncSetAttribute(qkv_gemm_f16, cudaFuncAttributeMaxDynamicSharedMemorySize, smem_gemm);
    cudaFuncSetAttribute(proj_gemm_f16, cudaFuncAttributeMaxDynamicSharedMemorySize, smem_gemm);

    bm_kernel<<<dim3(NTOK, NWIN * NHEADS), 128>>>(rpb, mask);
    qkv_gemm_f16<<<dim3(QKVN / 64, MROWS / 128), 256, smem_gemm>>>(x, qkv_w, qkv_b);
    attn_tc<<<dim3(NHEADS, NB), 512, smem_attn>>>();
    proj_gemm_f16<<<dim3(DIMC / 64, MROWS / 128), 256, smem_gemm>>>(proj_w, proj_b, out);
}

// round 11
// speedup vs baseline: 5.1290x; 1.3679x over previous
#include <cuda_runtime.h>
#include <cuda_fp16.h>
#include <math.h>

#define NHEADS 6
#define NTOK   343
#define DIMC   192
#define HD     32
#define NB     256
#define NWIN   64
#define MROWS  (NB*NTOK)      // 87808
#define QKVN   576
#define SCALEF 0.17677669529663687f

#define KSTRH  40    // attn K/Q smem stride (halves)
#define QSTRH  40
#define VTSTRH 360   // attn V^T smem stride (halves)
#define BMSTR  352   // bm row stride (floats)
#define XSTR   200   // gemm smem row stride (halves)

// ---- scratch (device globals; no runtime allocation) ----
__device__ __half g_q[(size_t)NB*NHEADS*NTOK*HD];
__device__ __half g_k[(size_t)NB*NHEADS*NTOK*HD];
__device__ __half g_v[(size_t)NB*NHEADS*NTOK*HD];
__device__ float  g_bm[(size_t)NWIN*NHEADS*NTOK*BMSTR];
__device__ __half g_ao[(size_t)NB*NTOK*DIMC];

__device__ __forceinline__ void mma_f16(float* c, const unsigned* a, unsigned b0, unsigned b1) {
    asm volatile(
        "mma.sync.aligned.m16n8k16.row.col.f32.f16.f16.f32 "
        "{%0,%1,%2,%3}, {%4,%5,%6,%7}, {%8,%9}, {%0,%1,%2,%3};"
        : "+f"(c[0]), "+f"(c[1]), "+f"(c[2]), "+f"(c[3])
        : "r"(a[0]), "r"(a[1]), "r"(a[2]), "r"(a[3]), "r"(b0), "r"(b1));
}

__device__ __forceinline__ unsigned pack_h2(float a, float b) {
    __half2 h = __floats2half2_rn(a, b);
    return *(unsigned*)&h;
}

// ---------------------------------------------------------------------------
// Kernel 1: fuse rpb gather + mask into g_bm[(w*6+h)][i][j], rows padded 352
// ---------------------------------------------------------------------------
__global__ void bm_kernel(const float* __restrict__ rpb, const float* __restrict__ mask)
{
    int i  = blockIdx.x;
    int wh = blockIdx.y;
    int w  = wh / NHEADS, h = wh - w * NHEADS;
    int di = i / 49, hi = (i / 7) % 7, wi = i % 7;
    float* dst = g_bm + ((size_t)wh * NTOK + i) * BMSTR;
    const float* mrow = mask + ((size_t)w * NTOK + i) * NTOK;
    for (int j = threadIdx.x; j < BMSTR; j += 128) {
        float val = 0.f;
        if (j < NTOK) {
            int dj = j / 49, hj = (j / 7) % 7, wj = j % 7;
            int idx = (di - dj + 6) * 169 + (hi - hj + 6) * 13 + (wi - wj + 6);
            val = rpb[idx * NHEADS + h] + mrow[j];
        }
        dst[j] = val;
    }
}

// ---------------------------------------------------------------------------
// Kernel 2: fp16-MMA QKV GEMM [MROWS x 192] @ W^T[192 x 576] (+bias), scatter.
// ---------------------------------------------------------------------------
__global__ __launch_bounds__(256) void qkv_gemm_f16(const float* __restrict__ X,
                                                    const float* __restrict__ W,
                                                    const float* __restrict__ bias)
{
    extern __shared__ __half gs[];
    __half* Xs = gs;                 // 128 x XSTR
    __half* Ws = gs + 128 * XSTR;    // 64  x XSTR
    int tid = threadIdx.x, lane = tid & 31, warp = tid >> 5;
    int gid = lane >> 2, qd = lane & 3;
    int m0 = blockIdx.y * 128, n0 = blockIdx.x * 64;
    int mrow = (warp & 3) * 32, ncol = (warp >> 2) * 32;

    for (int idx = tid; idx < 128 * 48; idx += 256) {
        int r = idx / 48, c4 = idx % 48;
        float4 v = *(const float4*)&X[(size_t)(m0 + r) * DIMC + c4 * 4];
        *(__half2*)&Xs[r * XSTR + c4 * 4]     = __floats2half2_rn(v.x, v.y);
        *(__half2*)&Xs[r * XSTR + c4 * 4 + 2] = __floats2half2_rn(v.z, v.w);
    }
    for (int idx = tid; idx < 64 * 48; idx += 256) {
        int r = idx / 48, c4 = idx % 48;
        float4 v = *(const float4*)&W[(size_t)(n0 + r) * DIMC + c4 * 4];
        *(__half2*)&Ws[r * XSTR + c4 * 4]     = __floats2half2_rn(v.x, v.y);
        *(__half2*)&Ws[r * XSTR + c4 * 4 + 2] = __floats2half2_rn(v.z, v.w);
    }
    __syncthreads();

    float c[2][4][4];
    #pragma unroll
    for (int mt = 0; mt < 2; mt++)
        #pragma unroll
        for (int nt = 0; nt < 4; nt++)
            #pragma unroll
            for (int i = 0; i < 4; i++) c[mt][nt][i] = 0.f;

    #pragma unroll
    for (int ks = 0; ks < 12; ks++) {
        int kk = ks * 16;
        unsigned a[2][4], bf[4][2];
        #pragma unroll
        for (int mt = 0; mt < 2; mt++) {
            int r = mrow + mt * 16 + gid;
            a[mt][0] = *(const unsigned*)&Xs[r * XSTR + kk + 2 * qd];
            a[mt][1] = *(const unsigned*)&Xs[(r + 8) * XSTR + kk + 2 * qd];
            a[mt][2] = *(const unsigned*)&Xs[r * XSTR + kk + 8 + 2 * qd];
            a[mt][3] = *(const unsigned*)&Xs[(r + 8) * XSTR + kk + 8 + 2 * qd];
        }
        #pragma unroll
        for (int nt = 0; nt < 4; nt++) {
            int rn = ncol + nt * 8 + gid;
            bf[nt][0] = *(const unsigned*)&Ws[rn * XSTR + kk + 2 * qd];
            bf[nt][1] = *(const unsigned*)&Ws[rn * XSTR + kk + 8 + 2 * qd];
        }
        #pragma unroll
        for (int mt = 0; mt < 2; mt++)
            #pragma unroll
            for (int nt = 0; nt < 4; nt++)
                mma_f16(c[mt][nt], a[mt], bf[nt][0], bf[nt][1]);
    }

    #pragma unroll
    for (int mt = 0; mt < 2; mt++) {
        int gmA = m0 + mrow + mt * 16 + gid, gmB = gmA + 8;
        int bA = gmA / NTOK, tA = gmA - bA * NTOK;
        int bB = gmB / NTOK, tB = gmB - bB * NTOK;
        #pragma unroll
        for (int nt = 0; nt < 4; nt++) {
            int gn = n0 + ncol + nt * 8 + 2 * qd;
            int sec = gn / DIMC, rem = gn - sec * DIMC;
            int hh = rem >> 5, dd = rem & 31;
            float b0 = bias[gn], b1 = bias[gn + 1];
            float vA0 = c[mt][nt][0] + b0, vA1 = c[mt][nt][1] + b1;
            float vB0 = c[mt][nt][2] + b0, vB1 = c[mt][nt][3] + b1;
            size_t offA = (((size_t)bA * NHEADS + hh) * NTOK + tA) * HD + dd;
            size_t offB = (((size_t)bB * NHEADS + hh) * NTOK + tB) * HD + dd;
            if (sec == 0) {
                *(__half2*)&g_q[offA] = __floats2half2_rn(vA0 * SCALEF, vA1 * SCALEF);
                *(__half2*)&g_q[offB] = __floats2half2_rn(vB0 * SCALEF, vB1 * SCALEF);
            } else if (sec == 1) {
                *(__half2*)&g_k[offA] = __floats2half2_rn(vA0, vA1);
                *(__half2*)&g_k[offB] = __floats2half2_rn(vB0, vB1);
            } else {
                *(__half2*)&g_v[offA] = __floats2half2_rn(vA0, vA1);
                *(__half2*)&g_v[offB] = __floats2half2_rn(vB0, vB1);
            }
        }
    }
}

// ---------------------------------------------------------------------------
// Kernel 3: fp16 register-resident flash attention, 2 blocks/SM.
// bm values arrive via prefetched registers (cur[4]); next loads issued by caller.
// ---------------------------------------------------------------------------
template<bool MASK>
__device__ __forceinline__ void attn_pair(int pr, int gid, int qd,
                                          const __half* __restrict__ Ks,
                                          const __half* __restrict__ Vt,
                                          const float2 cur[4],
                                          const unsigned a[2][4], float occ[4][4],
                                          float& m0, float& m1, float& s0, float& s1)
{
    int kb0 = pr * 16;
    float c[2][4];
    #pragma unroll
    for (int sub = 0; sub < 2; sub++) {
        c[sub][0] = c[sub][1] = c[sub][2] = c[sub][3] = 0.f;
        int kb = kb0 + sub * 8;
        const __half* krow = &Ks[(kb + gid) * KSTRH + 2 * qd];
        #pragma unroll
        for (int ks = 0; ks < 2; ks++) {
            unsigned b0 = *(const unsigned*)&krow[ks * 16];
            unsigned b1 = *(const unsigned*)&krow[ks * 16 + 8];
            mma_f16(c[sub], a[ks], b0, b1);
        }
        float2 mA = cur[sub * 2];
        float2 mB = cur[sub * 2 + 1];
        c[sub][0] += mA.x; c[sub][1] += mA.y;
        c[sub][2] += mB.x; c[sub][3] += mB.y;
        if (MASK) {
            int k0 = kb + 2 * qd;
            if (k0 >= NTOK)     { c[sub][0] = -1e30f; c[sub][2] = -1e30f; }
            if (k0 + 1 >= NTOK) { c[sub][1] = -1e30f; c[sub][3] = -1e30f; }
        }
    }
    float cm0 = fmaxf(fmaxf(c[0][0], c[0][1]), fmaxf(c[1][0], c[1][1]));
    float cm1 = fmaxf(fmaxf(c[0][2], c[0][3]), fmaxf(c[1][2], c[1][3]));
    cm0 = fmaxf(cm0, __shfl_xor_sync(0xffffffffu, cm0, 1));
    cm0 = fmaxf(cm0, __shfl_xor_sync(0xffffffffu, cm0, 2));
    cm1 = fmaxf(cm1, __shfl_xor_sync(0xffffffffu, cm1, 1));
    cm1 = fmaxf(cm1, __shfl_xor_sync(0xffffffffu, cm1, 2));
    float mn0 = fmaxf(m0, cm0), mn1 = fmaxf(m1, cm1);
    float sc0 = __expf(m0 - mn0), sc1 = __expf(m1 - mn1);
    m0 = mn0; m1 = mn1;
    s0 *= sc0; s1 *= sc1;
    #pragma unroll
    for (int nh = 0; nh < 4; nh++) {
        occ[nh][0] *= sc0; occ[nh][1] *= sc0;
        occ[nh][2] *= sc1; occ[nh][3] *= sc1;
    }
    float e00 = __expf(c[0][0] - m0), e01 = __expf(c[0][1] - m0);
    float e02 = __expf(c[0][2] - m1), e03 = __expf(c[0][3] - m1);
    float e10 = __expf(c[1][0] - m0), e11 = __expf(c[1][1] - m0);
    float e12 = __expf(c[1][2] - m1), e13 = __expf(c[1][3] - m1);
    s0 += e00 + e01 + e10 + e11;
    s1 += e02 + e03 + e12 + e13;
    unsigned pa[4];
    pa[0] = pack_h2(e00, e01);
    pa[1] = pack_h2(e02, e03);
    pa[2] = pack_h2(e10, e11);
    pa[3] = pack_h2(e12, e13);
    #pragma unroll
    for (int nh = 0; nh < 4; nh++) {
        const __half* vrow = &Vt[(nh * 8 + gid) * VTSTRH + kb0 + 2 * qd];
        unsigned b0 = *(const unsigned*)&vrow[0];
        unsigned b1 = *(const unsigned*)&vrow[8];
        mma_f16(occ[nh], pa, b0, b1);
    }
}

__global__ __launch_bounds__(512, 2) void attn_tc()
{
    extern __shared__ __half smh[];
    __half* Ks = smh;                      // 352*40 [key][hd]
    __half* Vt = Ks + 352 * KSTRH;         // 32*360 [hd][key]
    __half* Qs = Vt + 32 * VTSTRH;         // 352*40 [q][hd]

    int tid  = threadIdx.x;
    int h    = blockIdx.x;
    // L2-locality remap: the 4 images sharing window w get ADJACENT block ids
    int by   = blockIdx.y;
    int b    = ((by & 3) << 6) | (by >> 2);    // img = by&3, w = by>>2
    int w    = b & (NWIN - 1);
    int lane = tid & 31, warp = tid >> 5;
    int gid  = lane >> 2, qd = lane & 3;

    size_t base = (((size_t)b * NHEADS) + h) * NTOK * HD;
    const __half* qg = g_q + base;
    const __half* kg = g_k + base;
    const __half* vg = g_v + base;
    const float*  bm = g_bm + (size_t)(w * NHEADS + h) * NTOK * BMSTR;

    __half2 zero2 = __floats2half2_rn(0.f, 0.f);
    for (int i = tid; i < 352 * 16; i += 512) {
        int j = i >> 4, d2 = (i & 15) * 2;
        __half2 kv = zero2, vv = zero2;
        if (j < NTOK) {
            kv = *(const __half2*)&kg[j * HD + d2];
            vv = *(const __half2*)&vg[j * HD + d2];
        }
        *(__half2*)&Ks[j * KSTRH + d2] = kv;
        Vt[d2 * VTSTRH + j]       = __low2half(vv);
        Vt[(d2 + 1) * VTSTRH + j] = __high2half(vv);
        int t = j > NTOK - 1 ? NTOK - 1 : j;
        *(__half2*)&Qs[j * QSTRH + d2] = *(const __half2*)&qg[t * HD + d2];
    }
    __syncthreads();

    for (int wt = warp; wt < 22; wt += 16) {
        int r0 = wt * 16 + gid, r1 = r0 + 8;
        int tA = r0 > NTOK - 1 ? NTOK - 1 : r0;
        int tB = r1 > NTOK - 1 ? NTOK - 1 : r1;

        unsigned a[2][4];
        #pragma unroll
        for (int ks = 0; ks < 2; ks++) {
            a[ks][0] = *(const unsigned*)&Qs[r0 * QSTRH + ks * 16 + 2 * qd];
            a[ks][1] = *(const unsigned*)&Qs[r1 * QSTRH + ks * 16 + 2 * qd];
            a[ks][2] = *(const unsigned*)&Qs[r0 * QSTRH + ks * 16 + 8 + 2 * qd];
            a[ks][3] = *(const unsigned*)&Qs[r1 * QSTRH + ks * 16 + 8 + 2 * qd];
        }
        float occ[4][4];
        #pragma unroll
        for (int nh = 0; nh < 4; nh++)
            #pragma unroll
            for (int i = 0; i < 4; i++) occ[nh][i] = 0.f;
        float m0 = -1e30f, m1 = -1e30f, s0 = 0.f, s1 = 0.f;

        const float* bmA = bm + (size_t)tA * BMSTR + 2 * qd;
        const float* bmB = bm + (size_t)tB * BMSTR + 2 * qd;

        // prefetch bm for pr=0
        float2 pf[4];
        pf[0] = *(const float2*)&bmA[0];
        pf[1] = *(const float2*)&bmB[0];
        pf[2] = *(const float2*)&bmA[8];
        pf[3] = *(const float2*)&bmB[8];

        #pragma unroll 1
        for (int pr = 0; pr < 21; pr++) {
            float2 cur[4] = { pf[0], pf[1], pf[2], pf[3] };
            int nk = (pr + 1) * 16;
            pf[0] = *(const float2*)&bmA[nk];
            pf[1] = *(const float2*)&bmB[nk];
            pf[2] = *(const float2*)&bmA[nk + 8];
            pf[3] = *(const float2*)&bmB[nk + 8];
            attn_pair<false>(pr, gid, qd, Ks, Vt, cur, a, occ, m0, m1, s0, s1);
        }
        attn_pair<true>(21, gid, qd, Ks, Vt, pf, a, occ, m0, m1, s0, s1);

        s0 += __shfl_xor_sync(0xffffffffu, s0, 1);
        s0 += __shfl_xor_sync(0xffffffffu, s0, 2);
        s1 += __shfl_xor_sync(0xffffffffu, s1, 1);
        s1 += __shfl_xor_sync(0xffffffffu, s1, 2);
        float i0 = 1.f / s0, i1 = 1.f / s1;

        #pragma unroll
        for (int nh = 0; nh < 4; nh++) {
            int col = h * HD + nh * 8 + 2 * qd;
            if (r0 < NTOK)
                *(__half2*)&g_ao[((size_t)b * NTOK + r0) * DIMC + col] =
                    __floats2half2_rn(occ[nh][0] * i0, occ[nh][1] * i0);
            if (r1 < NTOK)
                *(__half2*)&g_ao[((size_t)b * NTOK + r1) * DIMC + col] =
                    __floats2half2_rn(occ[nh][2] * i1, occ[nh][3] * i1);
        }
    }
}

// ---------------------------------------------------------------------------
// Kernel 4: fp16-MMA projection GEMM [MROWS x 192] @ [192 x 192] (+bias).
// ---------------------------------------------------------------------------
__global__ __launch_bounds__(256) void proj_gemm_f16(const float* __restrict__ W,
                                                     const float* __restrict__ bias,
                                                     float* __restrict__ out)
{
    extern __shared__ __half gs[];
    __half* As = gs;                 // 128 x XSTR
    __half* Ws = gs + 128 * XSTR;    // 64  x XSTR
    int tid = threadIdx.x, lane = tid & 31, warp = tid >> 5;
    int gid = lane >> 2, qd = lane & 3;
    int m0 = blockIdx.y * 128, n0 = blockIdx.x * 64;
    int mrow = (warp & 3) * 32, ncol = (warp >> 2) * 32;

    for (int idx = tid; idx < 128 * 48; idx += 256) {
        int r = idx / 48, c4 = idx % 48;
        uint2 v = *(const uint2*)&g_ao[(size_t)(m0 + r) * DIMC + c4 * 4];
        *(uint2*)&As[r * XSTR + c4 * 4] = v;
    }
    for (int idx = tid; idx < 64 * 48; idx += 256) {
        int r = idx / 48, c4 = idx % 48;
        float4 v = *(const float4*)&W[(size_t)(n0 + r) * DIMC + c4 * 4];
        *(__half2*)&Ws[r * XSTR + c4 * 4]     = __floats2half2_rn(v.x, v.y);
        *(__half2*)&Ws[r * XSTR + c4 * 4 + 2] = __floats2half2_rn(v.z, v.w);
    }
    __syncthreads();

    float c[2][4][4];
    #pragma unroll
    for (int mt = 0; mt < 2; mt++)
        #pragma unroll
        for (int nt = 0; nt < 4; nt++)
            #pragma unroll
            for (int i = 0; i < 4; i++) c[mt][nt][i] = 0.f;

    #pragma unroll
    for (int ks = 0; ks < 12; ks++) {
        int kk = ks * 16;
        unsigned a[2][4], bf[4][2];
        #pragma unroll
        for (int mt = 0; mt < 2; mt++) {
            int r = mrow + mt * 16 + gid;
            a[mt][0] = *(const unsigned*)&As[r * XSTR + kk + 2 * qd];
            a[mt][1] = *(const unsigned*)&As[(r + 8) * XSTR + kk + 2 * qd];
            a[mt][2] = *(const unsigned*)&As[r * XSTR + kk + 8 + 2 * qd];
            a[mt][3] = *(const unsigned*)&As[(r + 8) * XSTR + kk + 8 + 2 * qd];
        }
        #pragma unroll
        for (int nt = 0; nt < 4; nt++) {
            int rn = ncol + nt * 8 + gid;
            bf[nt][0] = *(const unsigned*)&Ws[rn * XSTR + kk + 2 * qd];
            bf[nt][1] = *(const unsigned*)&Ws[rn * XSTR + kk + 8 + 2 * qd];
        }
        #pragma unroll
        for (int mt = 0; mt < 2; mt++)
            #pragma unroll
            for (int nt = 0; nt < 4; nt++)
                mma_f16(c[mt][nt], a[mt], bf[nt][0], bf[nt][1]);
    }

    #pragma unroll
    for (int mt = 0; mt < 2; mt++) {
        int gmA = m0 + mrow + mt * 16 + gid, gmB = gmA + 8;
        #pragma unroll
        for (int nt = 0; nt < 4; nt++) {
            int gn = n0 + ncol + nt * 8 + 2 * qd;
            float b0 = bias[gn], b1 = bias[gn + 1];
            *(float2*)&out[(size_t)gmA * DIMC + gn] =
                make_float2(c[mt][nt][0] + b0, c[mt][nt][1] + b1);
            *(float2*)&out[(size_t)gmB * DIMC + gn] =
                make_float2(c[mt][nt][2] + b0, c[mt][nt][3] + b1);
        }
    }
}

// ---------------------------------------------------------------------------
extern "C" void kernel_launch(void* const* d_in, const int* in_sizes, int n_in,
                              void* d_out, int out_size)
{
    const float* x      = (const float*)d_in[0];
    const float* mask   = (const float*)d_in[1];
    const float* qkv_w  = (const float*)d_in[2];
    const float* qkv_b  = (const float*)d_in[3];
    const float* rpb    = (const float*)d_in[4];
    const float* proj_w = (const float*)d_in[5];
    const float* proj_b = (const float*)d_in[6];
    float* out = (float*)d_out;

    (void)in_sizes; (void)n_in; (void)out_size;

    int smem_attn = (352 * KSTRH + 32 * VTSTRH + 352 * QSTRH) * (int)sizeof(__half);
    int smem_gemm = 192 * XSTR * (int)sizeof(__half);
    cudaFuncSetAttribute(attn_tc, cudaFuncAttributeMaxDynamicSharedMemorySize, smem_attn);
    cudaFuncSetAttribute(qkv_gemm_f16, cudaFuncAttributeMaxDynamicSharedMemorySize, smem_gemm);
    cudaFuncSetAttribute(proj_gemm_f16, cudaFuncAttributeMaxDynamicSharedMemorySize, smem_gemm);

    bm_kernel<<<dim3(NTOK, NWIN * NHEADS), 128>>>(rpb, mask);
    qkv_gemm_f16<<<dim3(QKVN / 64, MROWS / 128), 256, smem_gemm>>>(x, qkv_w, qkv_b);
    attn_tc<<<dim3(NHEADS, NB), 512, smem_attn>>>();
    proj_gemm_f16<<<dim3(DIMC / 64, MROWS / 128), 256, smem_gemm>>>(proj_w, proj_b, out);
}